// round 6
// baseline (speedup 1.0000x reference)
#include <cuda_runtime.h>
#include <cstdint>
#include <cstddef>

// Problem constants
#define BB 4
#define SS 2048
#define EE 1024
#define HH 16
#define DD 64
#define MTOK (BB * SS)     // 8192
#define NQKV (3 * EE)      // 3072
#define SCALE 0.125f
#define NSLICE 16

// GEMM tiling
#define BK 32                          // fp32 K per chunk
#define RSTRIDE 20                     // b32 per smem row (16 b32 data + 4 pad)
#define TILE32 (128 * RSTRIDE)         // 2560 b32 per operand tile
#define A_HI 0
#define A_LO TILE32
#define B_HI (2 * TILE32)
#define B_LO (3 * TILE32)
#define STAGE32 (4 * TILE32)           // 10240 b32 per stage
#define SMEM_BYTES (2 * STAGE32 * 4)   // 81920 B (dynamic)

// ---------------------------------------------------------------------------
// Scratch
// ---------------------------------------------------------------------------
__device__ float g_q[MTOK * EE];
__device__ float g_k[BB * HH][SS][DD];
__device__ float g_v[BB * HH][SS][DD];
__device__ float g_mpart[NSLICE][BB * HH][DD][DD];
__device__ float g_m[BB][HH][DD][DD];
__device__ float g_pt[BB][EE][EE];     // P^T [b][n][k]

// ---------------------------------------------------------------------------
// Helpers
// ---------------------------------------------------------------------------
__device__ __forceinline__ uint32_t smem_u32(const void* p) {
    uint32_t a;
    asm("{ .reg .u64 t; cvta.to.shared.u64 t, %1; cvt.u32.u64 %0, t; }" : "=r"(a) : "l"(p));
    return a;
}
__device__ __forceinline__ void mma_bf16(float* c, const uint32_t* a, const uint32_t* b) {
    asm volatile(
        "mma.sync.aligned.m16n8k16.row.col.f32.bf16.bf16.f32 "
        "{%0,%1,%2,%3}, {%4,%5,%6,%7}, {%8,%9}, {%0,%1,%2,%3};"
        : "+f"(c[0]), "+f"(c[1]), "+f"(c[2]), "+f"(c[3])
        : "r"(a[0]), "r"(a[1]), "r"(a[2]), "r"(a[3]), "r"(b[0]), "r"(b[1]));
}
__device__ __forceinline__ void ldm_x4(uint32_t& r0, uint32_t& r1, uint32_t& r2,
                                       uint32_t& r3, uint32_t addr) {
    asm volatile("ldmatrix.sync.aligned.m8n8.x4.shared.b16 {%0,%1,%2,%3}, [%4];"
                 : "=r"(r0), "=r"(r1), "=r"(r2), "=r"(r3) : "r"(addr));
}

// Split float4 into packed bf16 hi pair-regs and lo pair-regs (elem0 in low half).
__device__ __forceinline__ void split4(float4 v, uint32_t& h0, uint32_t& h1,
                                       uint32_t& l0, uint32_t& l1) {
    asm("cvt.rn.bf16x2.f32 %0, %1, %2;" : "=r"(h0) : "f"(v.y), "f"(v.x));
    asm("cvt.rn.bf16x2.f32 %0, %1, %2;" : "=r"(h1) : "f"(v.w), "f"(v.z));
    float hx = __uint_as_float(h0 << 16);
    float hy = __uint_as_float(h0 & 0xFFFF0000u);
    float hz = __uint_as_float(h1 << 16);
    float hw = __uint_as_float(h1 & 0xFFFF0000u);
    asm("cvt.rn.bf16x2.f32 %0, %1, %2;" : "=r"(l0) : "f"(v.y - hy), "f"(v.x - hx));
    asm("cvt.rn.bf16x2.f32 %0, %1, %2;" : "=r"(l1) : "f"(v.w - hw), "f"(v.z - hz));
}

// ---------------------------------------------------------------------------
// bf16x2-split tensor-core GEMM with ldmatrix fragment loads.
// C tiles 128x128, BK=32, 256 threads, 8 warps (warp tile 32x64).
// A: [m][k] K-contig. B: [n][k] K-contig.
// MODE 0: qkv (scatter epilogue). MODE 1: out (direct epilogue).
// ---------------------------------------------------------------------------
template <int MODE>
__global__ __launch_bounds__(256, 2) void gemm_mma(const float* __restrict__ A,
                                                   const float* __restrict__ Bmat,
                                                   float* __restrict__ Out) {
    extern __shared__ uint32_t sm32[];
    const int tid = threadIdx.x;
    const int wid = tid >> 5, lane = tid & 31;
    const int g = lane >> 2, tg = lane & 3;
    const int warp_m = wid & 3;
    const int warp_n = wid >> 2;
    const int bn = blockIdx.x * 128;
    const int bm = blockIdx.y * 128;

    const float* Ap;
    const float* Bp;
    if (MODE == 0) {
        Ap = A + (size_t)bm * EE;
        Bp = Bmat + (size_t)bn * EE;
    } else {
        const int batch = bm >> 11;
        Ap = &g_q[0] + (size_t)bm * EE;
        Bp = &g_pt[0][0][0] + ((size_t)batch * EE + bn) * EE;
    }

    const uint32_t sb = smem_u32(sm32);

    // ldmatrix per-lane address components (b32 indices; *4 for bytes)
    const int arow = ((lane >> 3) & 1) * 8 + (lane & 7);
    const int ahalf = lane >> 4;                        // 0/1 -> k half
    const int aRowOff = (warp_m * 32 + arow) * RSTRIDE + ahalf * 4;
    const int brow = ((lane >> 4) & 1) * 8 + (lane & 7);
    const int bhalf = (lane >> 3) & 1;
    const int bRowOff = (warp_n * 64 + brow) * RSTRIDE + bhalf * 4;

    float acc[2][8][4];
#pragma unroll
    for (int mt = 0; mt < 2; ++mt)
#pragma unroll
        for (int nt = 0; nt < 8; ++nt)
#pragma unroll
            for (int i = 0; i < 4; ++i) acc[mt][nt][i] = 0.0f;

    // Prefetch registers: 4 float4 of A + 4 of B per thread per chunk.
    float4 pa[4], pb[4];
    const int prow = tid >> 3;
    const int pc4 = (tid & 7) * 4;

    auto ldg_chunk = [&](int k0) {
#pragma unroll
        for (int i = 0; i < 4; ++i) {
            const int row = prow + i * 32;
            pa[i] = *(const float4*)(Ap + (size_t)row * EE + k0 + pc4);
            pb[i] = *(const float4*)(Bp + (size_t)row * EE + k0 + pc4);
        }
    };
    auto sts_chunk = [&](int s) {
        uint32_t* st = sm32 + s * STAGE32;
#pragma unroll
        for (int i = 0; i < 4; ++i) {
            const int row = prow + i * 32;
            const int off = row * RSTRIDE + (pc4 >> 1);
            uint32_t h0, h1, l0, l1;
            split4(pa[i], h0, h1, l0, l1);
            st[A_HI + off] = h0; st[A_HI + off + 1] = h1;
            st[A_LO + off] = l0; st[A_LO + off + 1] = l1;
            split4(pb[i], h0, h1, l0, l1);
            st[B_HI + off] = h0; st[B_HI + off + 1] = h1;
            st[B_LO + off] = l0; st[B_LO + off + 1] = l1;
        }
    };

    ldg_chunk(0);

    const int NK = EE / BK;   // 32
    for (int kc = 0; kc < NK; ++kc) {
        const int s = kc & 1;
        sts_chunk(s);
        __syncthreads();
        if (kc + 1 < NK) ldg_chunk((kc + 1) * BK);

        const uint32_t stage4 = sb + (s * STAGE32) * 4;   // byte base of stage
#pragma unroll
        for (int ks = 0; ks < 2; ++ks) {
            uint32_t ahi[2][4], alo[2][4], bhi[8][2], blo[8][2];
#pragma unroll
            for (int mt = 0; mt < 2; ++mt) {
                const uint32_t ao = stage4 + (mt * 16 * RSTRIDE + ks * 8 + aRowOff) * 4;
                ldm_x4(ahi[mt][0], ahi[mt][1], ahi[mt][2], ahi[mt][3], ao + A_HI * 4);
                ldm_x4(alo[mt][0], alo[mt][1], alo[mt][2], alo[mt][3], ao + A_LO * 4);
            }
#pragma unroll
            for (int p = 0; p < 4; ++p) {
                const uint32_t bo = stage4 + (p * 16 * RSTRIDE + ks * 8 + bRowOff) * 4;
                ldm_x4(bhi[2 * p][0], bhi[2 * p][1], bhi[2 * p + 1][0], bhi[2 * p + 1][1],
                       bo + B_HI * 4);
                ldm_x4(blo[2 * p][0], blo[2 * p][1], blo[2 * p + 1][0], blo[2 * p + 1][1],
                       bo + B_LO * 4);
            }
#pragma unroll
            for (int mt = 0; mt < 2; ++mt)
#pragma unroll
                for (int nt = 0; nt < 8; ++nt) mma_bf16(acc[mt][nt], ahi[mt], bhi[nt]);
#pragma unroll
            for (int mt = 0; mt < 2; ++mt)
#pragma unroll
                for (int nt = 0; nt < 8; ++nt) mma_bf16(acc[mt][nt], alo[mt], bhi[nt]);
#pragma unroll
            for (int mt = 0; mt < 2; ++mt)
#pragma unroll
                for (int nt = 0; nt < 8; ++nt) mma_bf16(acc[mt][nt], ahi[mt], blo[nt]);
        }
        __syncthreads();
    }

    // Epilogue: direct register -> gmem float2 stores.
#pragma unroll
    for (int mt = 0; mt < 2; ++mt) {
#pragma unroll
        for (int nt = 0; nt < 8; ++nt) {
            const int col = bn + warp_n * 64 + nt * 8 + 2 * tg;
#pragma unroll
            for (int half = 0; half < 2; ++half) {
                const int row = bm + warp_m * 32 + mt * 16 + g + half * 8;
                const float v0 = acc[mt][nt][half * 2 + 0];
                const float v1 = acc[mt][nt][half * 2 + 1];
                if (MODE == 1) {
                    *(float2*)&Out[(size_t)row * EE + col] = make_float2(v0, v1);
                } else {
                    const int h = col / 192;
                    const int jj = col - h * 192;
                    const int bidx = row >> 11;
                    const int sr = row & 2047;
                    if (jj < 64)
                        *(float2*)&g_q[(size_t)row * EE + h * 64 + jj] = make_float2(v0, v1);
                    else if (jj < 128)
                        *(float2*)&g_k[bidx * HH + h][sr][jj - 64] = make_float2(v0, v1);
                    else
                        *(float2*)&g_v[bidx * HH + h][sr][jj - 128] = make_float2(v0, v1);
                }
            }
        }
    }
}

// ---------------------------------------------------------------------------
// kv_reduce partials: grid (64, NSLICE); 64x64 partial K^T V over S/NSLICE rows.
// ---------------------------------------------------------------------------
__global__ __launch_bounds__(256) void kv_reduce() {
    const int bh = blockIdx.x;
    const int sl = blockIdx.y;
    const int tid = threadIdx.x;
    const int tx = tid & 15;
    const int ty = tid >> 4;

    __shared__ float Ks[32][64];
    __shared__ float Vs[32][64];

    float acc[4][4];
#pragma unroll
    for (int i = 0; i < 4; ++i)
#pragma unroll
        for (int j = 0; j < 4; ++j) acc[i][j] = 0.0f;

    const int s_beg = sl * (SS / NSLICE);
    for (int s0 = s_beg; s0 < s_beg + SS / NSLICE; s0 += 32) {
#pragma unroll
        for (int it = 0; it < 2; ++it) {
            const int fid = tid + it * 256;
            const int row = fid >> 4;
            const int c4 = (fid & 15) * 4;
            *(float4*)&Ks[row][c4] = *(const float4*)&g_k[bh][s0 + row][c4];
            *(float4*)&Vs[row][c4] = *(const float4*)&g_v[bh][s0 + row][c4];
        }
        __syncthreads();
#pragma unroll 8
        for (int s = 0; s < 32; ++s) {
            float a[4], b[4];
#pragma unroll
            for (int i = 0; i < 4; ++i) a[i] = Ks[s][ty * 4 + i];
#pragma unroll
            for (int j = 0; j < 4; ++j) b[j] = Vs[s][tx * 4 + j];
#pragma unroll
            for (int i = 0; i < 4; ++i)
#pragma unroll
                for (int j = 0; j < 4; ++j) acc[i][j] += a[i] * b[j];
        }
        __syncthreads();
    }
#pragma unroll
    for (int i = 0; i < 4; ++i)
#pragma unroll
        for (int j = 0; j < 4; ++j)
            g_mpart[sl][bh][ty * 4 + i][tx * 4 + j] = acc[i][j];
}

__global__ __launch_bounds__(256) void merge_m() {
    const int bh = blockIdx.x;
    const int b = bh / HH, h = bh % HH;
    for (int e = threadIdx.x; e < DD * DD; e += 256) {
        float s = 0.0f;
#pragma unroll
        for (int p = 0; p < NSLICE; ++p) s += g_mpart[p][bh][e >> 6][e & 63];
        g_m[b][h][e >> 6][e & 63] = SCALE * s;
    }
}

// ---------------------------------------------------------------------------
// make_p: g_pt[b][c][r] = sum_d M[b][h][rl][d] * w_o[c][h*64+d]  (r = h*64+rl)
// Grid (EE/64, HH, BB). Tiles stored transposed (d-major) -> conflict-free.
// ---------------------------------------------------------------------------
__global__ __launch_bounds__(256) void make_p(const float* __restrict__ w_o) {
    const int h = blockIdx.y;
    const int b = blockIdx.z;
    const int c0 = blockIdx.x * 64;
    const int tid = threadIdx.x;
    const int tx = tid & 15;   // rl
    const int ty = tid >> 4;   // c

    __shared__ float Wost[64][68];   // [d][c]
    __shared__ float Mst[64][68];    // [d][rl]

#pragma unroll
    for (int it = 0; it < 4; ++it) {
        const int fid = tid + it * 256;
        const int c = fid >> 4;
        const int d4 = (fid & 15) * 4;
        float4 v = *(const float4*)&w_o[(size_t)(c0 + c) * EE + h * 64 + d4];
        Wost[d4 + 0][c] = v.x; Wost[d4 + 1][c] = v.y;
        Wost[d4 + 2][c] = v.z; Wost[d4 + 3][c] = v.w;
        float4 m = *(const float4*)&g_m[b][h][c][d4];   // c reused as rl (0..63)
        Mst[d4 + 0][c] = m.x; Mst[d4 + 1][c] = m.y;
        Mst[d4 + 2][c] = m.z; Mst[d4 + 3][c] = m.w;
    }
    __syncthreads();

    float acc[4][4];
#pragma unroll
    for (int i = 0; i < 4; ++i)
#pragma unroll
        for (int j = 0; j < 4; ++j) acc[i][j] = 0.0f;
#pragma unroll 8
    for (int d = 0; d < 64; ++d) {
        float a[4], bb[4];
#pragma unroll
        for (int i = 0; i < 4; ++i) a[i] = Wost[d][ty * 4 + i];
#pragma unroll
        for (int j = 0; j < 4; ++j) bb[j] = Mst[d][tx * 4 + j];
#pragma unroll
        for (int i = 0; i < 4; ++i)
#pragma unroll
            for (int j = 0; j < 4; ++j) acc[i][j] += a[i] * bb[j];
    }
#pragma unroll
    for (int i = 0; i < 4; ++i) {
        float4 v;
        v.x = acc[i][0]; v.y = acc[i][1]; v.z = acc[i][2]; v.w = acc[i][3];
        *(float4*)&g_pt[b][c0 + ty * 4 + i][h * 64 + tx * 4] = v;
    }
}

// ---------------------------------------------------------------------------
// Launch
// ---------------------------------------------------------------------------
extern "C" void kernel_launch(void* const* d_in, const int* in_sizes, int n_in,
                              void* d_out, int out_size) {
    const float* x = (const float*)d_in[0];
    const float* w_qkv = (const float*)d_in[1];
    const float* w_o = (const float*)d_in[2];
    float* out = (float*)d_out;

    cudaFuncSetAttribute(gemm_mma<0>, cudaFuncAttributeMaxDynamicSharedMemorySize, SMEM_BYTES);
    cudaFuncSetAttribute(gemm_mma<1>, cudaFuncAttributeMaxDynamicSharedMemorySize, SMEM_BYTES);

    gemm_mma<0><<<dim3(NQKV / 128, MTOK / 128), 256, SMEM_BYTES>>>(x, w_qkv, nullptr);
    kv_reduce<<<dim3(BB * HH, NSLICE), 256>>>();
    merge_m<<<BB * HH, 256>>>();
    make_p<<<dim3(EE / 64, HH, BB), 256>>>(w_o);
    gemm_mma<1><<<dim3(EE / 128, MTOK / 128), 256, SMEM_BYTES>>>(nullptr, nullptr, out);
}

// round 7
// speedup vs baseline: 1.4977x; 1.4977x over previous
#include <cuda_runtime.h>
#include <cstdint>
#include <cstddef>

// Problem constants
#define BB 4
#define SS 2048
#define EE 1024
#define HH 16
#define DD 64
#define MTOK (BB * SS)     // 8192
#define NQKV (3 * EE)      // 3072
#define SCALE 0.125f
#define NSLICE 16

// int8 GEMM tiling
#define BKB 64                          // K bytes per chunk
#define RSTR 80                         // bytes per smem row (64 data + 16 pad)
#define TILEB (128 * RSTR)              // 10240 B per limb tile
#define STAGEB (4 * TILEB)              // A1 A2 B1 B2
#define SMEM_BYTES (2 * STAGEB)         // 81920 B

// ---------------------------------------------------------------------------
// Scratch
// ---------------------------------------------------------------------------
__device__ float g_q[MTOK * EE];
__device__ float g_k[BB * HH][SS][DD];
__device__ float g_v[BB * HH][SS][DD];
__device__ float g_mpart[NSLICE][BB * HH][DD][DD];
__device__ float g_m[BB][HH][DD][DD];
__device__ float g_pt[BB][EE][EE];     // P^T [b][n][k]

__device__ unsigned char g_xa1[MTOK * EE], g_xa2[MTOK * EE];
__device__ unsigned char g_wb1[NQKV * EE], g_wb2[NQKV * EE];
__device__ unsigned char g_qa1[MTOK * EE], g_qa2[MTOK * EE];
__device__ unsigned char g_pb1[BB * EE * EE], g_pb2[BB * EE * EE];
__device__ float g_sx[MTOK], g_sw[NQKV], g_sq[MTOK], g_sp[BB * EE];

// ---------------------------------------------------------------------------
// Helpers
// ---------------------------------------------------------------------------
__device__ __forceinline__ uint32_t smem_u32(const void* p) {
    uint32_t a;
    asm("{ .reg .u64 t; cvta.to.shared.u64 t, %1; cvt.u32.u64 %0, t; }" : "=r"(a) : "l"(p));
    return a;
}
__device__ __forceinline__ void cpasync16(uint32_t s, const void* g) {
    asm volatile("cp.async.cg.shared.global [%0], [%1], 16;" :: "r"(s), "l"(g));
}
#define CP_COMMIT() asm volatile("cp.async.commit_group;" ::: "memory")
#define CP_WAIT(n)  asm volatile("cp.async.wait_group %0;" :: "n"(n) : "memory")

__device__ __forceinline__ void imma(int* c, const uint32_t* a, const uint32_t* b) {
    asm volatile(
        "mma.sync.aligned.m16n8k32.row.col.s32.s8.s8.s32 "
        "{%0,%1,%2,%3}, {%4,%5,%6,%7}, {%8,%9}, {%0,%1,%2,%3};"
        : "+r"(c[0]), "+r"(c[1]), "+r"(c[2]), "+r"(c[3])
        : "r"(a[0]), "r"(a[1]), "r"(a[2]), "r"(a[3]), "r"(b[0]), "r"(b[1]));
}

// ---------------------------------------------------------------------------
// Quantize rows of a [rows x 1024] fp32 matrix into two s8 limbs + scale.
// q1 = rint(v/s), q2 = rint((v/s - q1)*252), s = rowmax/126.
// One block per row, 256 threads, 4 floats per thread.
// ---------------------------------------------------------------------------
__global__ __launch_bounds__(256) void quantize(const float* __restrict__ src,
                                                unsigned char* __restrict__ q1,
                                                unsigned char* __restrict__ q2,
                                                float* __restrict__ sdeq) {
    const int row = blockIdx.x;
    const int tid = threadIdx.x;
    __shared__ float wmax[8];
    __shared__ float sinv;

    float4 v = *(const float4*)&src[(size_t)row * EE + tid * 4];
    float m = fmaxf(fmaxf(fabsf(v.x), fabsf(v.y)), fmaxf(fabsf(v.z), fabsf(v.w)));
#pragma unroll
    for (int o = 16; o > 0; o >>= 1) m = fmaxf(m, __shfl_xor_sync(0xFFFFFFFFu, m, o));
    if ((tid & 31) == 0) wmax[tid >> 5] = m;
    __syncthreads();
    if (tid == 0) {
        float mm = wmax[0];
#pragma unroll
        for (int i = 1; i < 8; ++i) mm = fmaxf(mm, wmax[i]);
        sdeq[row] = mm * (1.0f / 126.0f);
        sinv = (mm > 0.0f) ? 126.0f / mm : 0.0f;
    }
    __syncthreads();
    const float inv = sinv;

    int a[4], b[4];
    float t, e;
    t = v.x * inv; a[0] = __float2int_rn(t); e = t - (float)a[0]; b[0] = __float2int_rn(e * 252.0f);
    t = v.y * inv; a[1] = __float2int_rn(t); e = t - (float)a[1]; b[1] = __float2int_rn(e * 252.0f);
    t = v.z * inv; a[2] = __float2int_rn(t); e = t - (float)a[2]; b[2] = __float2int_rn(e * 252.0f);
    t = v.w * inv; a[3] = __float2int_rn(t); e = t - (float)a[3]; b[3] = __float2int_rn(e * 252.0f);

    uint32_t p1 = (a[0] & 0xFF) | ((a[1] & 0xFF) << 8) | ((a[2] & 0xFF) << 16) | ((uint32_t)(a[3] & 0xFF) << 24);
    uint32_t p2 = (b[0] & 0xFF) | ((b[1] & 0xFF) << 8) | ((b[2] & 0xFF) << 16) | ((uint32_t)(b[3] & 0xFF) << 24);
    ((uint32_t*)q1)[(size_t)row * 256 + tid] = p1;
    ((uint32_t*)q2)[(size_t)row * 256 + tid] = p2;
}

// ---------------------------------------------------------------------------
// int8 2-limb tensor-core GEMM. C tiles 128x128, BKB=64, 256 threads, 8 warps
// (warp tile 32x64). A limbs: [m][k] K-contig s8. B limbs: [n][k] K-contig s8.
// C = sA[m]*sB[n]*(P11 + Pmix/252).
// MODE 0: qkv (scatter epilogue). MODE 1: out (direct epilogue).
// ---------------------------------------------------------------------------
template <int MODE>
__global__ __launch_bounds__(256, 1) void gemm_i8(float* __restrict__ Out) {
    extern __shared__ unsigned char smem[];
    const int tid = threadIdx.x;
    const int wid = tid >> 5, lane = tid & 31;
    const int g = lane >> 2, tg = lane & 3;
    const int warp_m = wid & 3;
    const int warp_n = wid >> 2;
    const int bn = blockIdx.x * 128;
    const int bm = blockIdx.y * 128;

    const unsigned char *A1, *A2, *B1, *B2;
    const float *sA, *sB;
    if (MODE == 0) {
        A1 = g_xa1 + (size_t)bm * EE;  A2 = g_xa2 + (size_t)bm * EE;
        B1 = g_wb1 + (size_t)bn * EE;  B2 = g_wb2 + (size_t)bn * EE;
        sA = g_sx + bm;  sB = g_sw + bn;
    } else {
        const int batch = bm >> 11;
        A1 = g_qa1 + (size_t)bm * EE;  A2 = g_qa2 + (size_t)bm * EE;
        B1 = g_pb1 + ((size_t)batch * EE + bn) * EE;
        B2 = g_pb2 + ((size_t)batch * EE + bn) * EE;
        sA = g_sq + bm;  sB = g_sp + batch * EE + bn;
    }

    const uint32_t sb = smem_u32(smem);

    int acc11[2][8][4], accmx[2][8][4];
#pragma unroll
    for (int mt = 0; mt < 2; ++mt)
#pragma unroll
        for (int nt = 0; nt < 8; ++nt)
#pragma unroll
            for (int i = 0; i < 4; ++i) { acc11[mt][nt][i] = 0; accmx[mt][nt][i] = 0; }

    // cp.async loader: per limb tile 512 x 16B lines; 2 per thread per tile.
    auto load_chunk = [&](int s, int k0) {
        const uint32_t base = sb + s * STAGEB;
#pragma unroll
        for (int it = 0; it < 2; ++it) {
            const int id = tid + it * 256;
            const int row = id >> 2;
            const int c16 = (id & 3) * 16;
            const uint32_t so = row * RSTR + c16;
            const size_t go = (size_t)row * EE + k0 + c16;
            cpasync16(base + so,              A1 + go);
            cpasync16(base + TILEB + so,      A2 + go);
            cpasync16(base + 2 * TILEB + so,  B1 + go);
            cpasync16(base + 3 * TILEB + so,  B2 + go);
        }
        CP_COMMIT();
    };

    load_chunk(0, 0);

    const int NK = EE / BKB;   // 16
    for (int kc = 0; kc < NK; ++kc) {
        const int s = kc & 1;
        if (kc + 1 < NK) {
            load_chunk(1 - s, (kc + 1) * BKB);
            CP_WAIT(1);
        } else {
            CP_WAIT(0);
        }
        __syncthreads();

        const uint32_t stg = sb + s * STAGEB;
#pragma unroll
        for (int ks = 0; ks < 2; ++ks) {
            const uint32_t kof = ks * 32 + tg * 4;
            uint32_t a1f[2][4], a2f[2][4], b1f[8][2], b2f[8][2];
#pragma unroll
            for (int mt = 0; mt < 2; ++mt) {
                const uint32_t r0 = stg + (warp_m * 32 + mt * 16 + g) * RSTR + kof;
#pragma unroll
                for (int limb = 0; limb < 2; ++limb) {
                    uint32_t* f = limb ? a2f[mt] : a1f[mt];
                    const uint32_t rr = r0 + limb * TILEB;
                    asm volatile("ld.shared.b32 %0, [%1];" : "=r"(f[0]) : "r"(rr));
                    asm volatile("ld.shared.b32 %0, [%1];" : "=r"(f[1]) : "r"(rr + 8 * RSTR));
                    asm volatile("ld.shared.b32 %0, [%1];" : "=r"(f[2]) : "r"(rr + 16));
                    asm volatile("ld.shared.b32 %0, [%1];" : "=r"(f[3]) : "r"(rr + 8 * RSTR + 16));
                }
            }
#pragma unroll
            for (int nt = 0; nt < 8; ++nt) {
                const uint32_t r0 = stg + 2 * TILEB + (warp_n * 64 + nt * 8 + g) * RSTR + kof;
                asm volatile("ld.shared.b32 %0, [%1];" : "=r"(b1f[nt][0]) : "r"(r0));
                asm volatile("ld.shared.b32 %0, [%1];" : "=r"(b1f[nt][1]) : "r"(r0 + 16));
                asm volatile("ld.shared.b32 %0, [%1];" : "=r"(b2f[nt][0]) : "r"(r0 + TILEB));
                asm volatile("ld.shared.b32 %0, [%1];" : "=r"(b2f[nt][1]) : "r"(r0 + TILEB + 16));
            }
#pragma unroll
            for (int mt = 0; mt < 2; ++mt)
#pragma unroll
                for (int nt = 0; nt < 8; ++nt) imma(acc11[mt][nt], a1f[mt], b1f[nt]);
#pragma unroll
            for (int mt = 0; mt < 2; ++mt)
#pragma unroll
                for (int nt = 0; nt < 8; ++nt) imma(accmx[mt][nt], a1f[mt], b2f[nt]);
#pragma unroll
            for (int mt = 0; mt < 2; ++mt)
#pragma unroll
                for (int nt = 0; nt < 8; ++nt) imma(accmx[mt][nt], a2f[mt], b1f[nt]);
        }
        __syncthreads();
    }

    // Epilogue: dequant + store.
#pragma unroll
    for (int mt = 0; mt < 2; ++mt) {
        float sa0 = sA[warp_m * 32 + mt * 16 + g];
        float sa1 = sA[warp_m * 32 + mt * 16 + g + 8];
#pragma unroll
        for (int nt = 0; nt < 8; ++nt) {
            const int coff = warp_n * 64 + nt * 8 + 2 * tg;
            const float sb0 = sB[coff], sb1 = sB[coff + 1];
            const int col = bn + coff;
#pragma unroll
            for (int half = 0; half < 2; ++half) {
                const int row = bm + warp_m * 32 + mt * 16 + g + half * 8;
                const float sa = half ? sa1 : sa0;
                float v0 = ((float)acc11[mt][nt][half * 2 + 0]
                            + (float)accmx[mt][nt][half * 2 + 0] * (1.0f / 252.0f)) * sa * sb0;
                float v1 = ((float)acc11[mt][nt][half * 2 + 1]
                            + (float)accmx[mt][nt][half * 2 + 1] * (1.0f / 252.0f)) * sa * sb1;
                if (MODE == 1) {
                    *(float2*)&Out[(size_t)row * EE + col] = make_float2(v0, v1);
                } else {
                    const int h = col / 192;
                    const int jj = col - h * 192;
                    const int bidx = row >> 11;
                    const int sr = row & 2047;
                    if (jj < 64)
                        *(float2*)&g_q[(size_t)row * EE + h * 64 + jj] = make_float2(v0, v1);
                    else if (jj < 128)
                        *(float2*)&g_k[bidx * HH + h][sr][jj - 64] = make_float2(v0, v1);
                    else
                        *(float2*)&g_v[bidx * HH + h][sr][jj - 128] = make_float2(v0, v1);
                }
            }
        }
    }
}

// ---------------------------------------------------------------------------
// kv_reduce partials: grid (64, NSLICE); 64x64 partial K^T V over S/NSLICE rows.
// ---------------------------------------------------------------------------
__global__ __launch_bounds__(256) void kv_reduce() {
    const int bh = blockIdx.x;
    const int sl = blockIdx.y;
    const int tid = threadIdx.x;
    const int tx = tid & 15;
    const int ty = tid >> 4;

    __shared__ float Ks[32][64];
    __shared__ float Vs[32][64];

    float acc[4][4];
#pragma unroll
    for (int i = 0; i < 4; ++i)
#pragma unroll
        for (int j = 0; j < 4; ++j) acc[i][j] = 0.0f;

    const int s_beg = sl * (SS / NSLICE);
    for (int s0 = s_beg; s0 < s_beg + SS / NSLICE; s0 += 32) {
#pragma unroll
        for (int it = 0; it < 2; ++it) {
            const int fid = tid + it * 256;
            const int row = fid >> 4;
            const int c4 = (fid & 15) * 4;
            *(float4*)&Ks[row][c4] = *(const float4*)&g_k[bh][s0 + row][c4];
            *(float4*)&Vs[row][c4] = *(const float4*)&g_v[bh][s0 + row][c4];
        }
        __syncthreads();
#pragma unroll 8
        for (int s = 0; s < 32; ++s) {
            float a[4], b[4];
#pragma unroll
            for (int i = 0; i < 4; ++i) a[i] = Ks[s][ty * 4 + i];
#pragma unroll
            for (int j = 0; j < 4; ++j) b[j] = Vs[s][tx * 4 + j];
#pragma unroll
            for (int i = 0; i < 4; ++i)
#pragma unroll
                for (int j = 0; j < 4; ++j) acc[i][j] += a[i] * b[j];
        }
        __syncthreads();
    }
#pragma unroll
    for (int i = 0; i < 4; ++i)
#pragma unroll
        for (int j = 0; j < 4; ++j)
            g_mpart[sl][bh][ty * 4 + i][tx * 4 + j] = acc[i][j];
}

__global__ __launch_bounds__(256) void merge_m() {
    const int bh = blockIdx.x;
    const int b = bh / HH, h = bh % HH;
    for (int e = threadIdx.x; e < DD * DD; e += 256) {
        float s = 0.0f;
#pragma unroll
        for (int p = 0; p < NSLICE; ++p) s += g_mpart[p][bh][e >> 6][e & 63];
        g_m[b][h][e >> 6][e & 63] = SCALE * s;
    }
}

// ---------------------------------------------------------------------------
// make_p: g_pt[b][c][r] = sum_d M[b][h][rl][d] * w_o[c][h*64+d]  (r = h*64+rl)
// Grid (EE/64, HH, BB). Tiles stored transposed (d-major) -> conflict-free.
// ---------------------------------------------------------------------------
__global__ __launch_bounds__(256) void make_p(const float* __restrict__ w_o) {
    const int h = blockIdx.y;
    const int b = blockIdx.z;
    const int c0 = blockIdx.x * 64;
    const int tid = threadIdx.x;
    const int tx = tid & 15;   // rl
    const int ty = tid >> 4;   // c

    __shared__ float Wost[64][68];   // [d][c]
    __shared__ float Mst[64][68];    // [d][rl]

#pragma unroll
    for (int it = 0; it < 4; ++it) {
        const int fid = tid + it * 256;
        const int c = fid >> 4;
        const int d4 = (fid & 15) * 4;
        float4 v = *(const float4*)&w_o[(size_t)(c0 + c) * EE + h * 64 + d4];
        Wost[d4 + 0][c] = v.x; Wost[d4 + 1][c] = v.y;
        Wost[d4 + 2][c] = v.z; Wost[d4 + 3][c] = v.w;
        float4 m = *(const float4*)&g_m[b][h][c][d4];
        Mst[d4 + 0][c] = m.x; Mst[d4 + 1][c] = m.y;
        Mst[d4 + 2][c] = m.z; Mst[d4 + 3][c] = m.w;
    }
    __syncthreads();

    float acc[4][4];
#pragma unroll
    for (int i = 0; i < 4; ++i)
#pragma unroll
        for (int j = 0; j < 4; ++j) acc[i][j] = 0.0f;
#pragma unroll 8
    for (int d = 0; d < 64; ++d) {
        float a[4], bb[4];
#pragma unroll
        for (int i = 0; i < 4; ++i) a[i] = Wost[d][ty * 4 + i];
#pragma unroll
        for (int j = 0; j < 4; ++j) bb[j] = Mst[d][tx * 4 + j];
#pragma unroll
        for (int i = 0; i < 4; ++i)
#pragma unroll
            for (int j = 0; j < 4; ++j) acc[i][j] += a[i] * bb[j];
    }
#pragma unroll
    for (int i = 0; i < 4; ++i) {
        float4 v;
        v.x = acc[i][0]; v.y = acc[i][1]; v.z = acc[i][2]; v.w = acc[i][3];
        *(float4*)&g_pt[b][c0 + ty * 4 + i][h * 64 + tx * 4] = v;
    }
}

// ---------------------------------------------------------------------------
// Launch
// ---------------------------------------------------------------------------
extern "C" void kernel_launch(void* const* d_in, const int* in_sizes, int n_in,
                              void* d_out, int out_size) {
    const float* x = (const float*)d_in[0];
    const float* w_qkv = (const float*)d_in[1];
    const float* w_o = (const float*)d_in[2];
    float* out = (float*)d_out;

    cudaFuncSetAttribute(gemm_i8<0>, cudaFuncAttributeMaxDynamicSharedMemorySize, SMEM_BYTES);
    cudaFuncSetAttribute(gemm_i8<1>, cudaFuncAttributeMaxDynamicSharedMemorySize, SMEM_BYTES);

    // Resolve device-global scratch addresses (host-side) once per launch.
    unsigned char *xa1, *xa2, *wb1, *wb2, *qa1, *qa2, *pb1, *pb2;
    float *sx, *sw, *sq, *sp, *qf, *ptf;
    cudaGetSymbolAddress((void**)&xa1, g_xa1);
    cudaGetSymbolAddress((void**)&xa2, g_xa2);
    cudaGetSymbolAddress((void**)&wb1, g_wb1);
    cudaGetSymbolAddress((void**)&wb2, g_wb2);
    cudaGetSymbolAddress((void**)&qa1, g_qa1);
    cudaGetSymbolAddress((void**)&qa2, g_qa2);
    cudaGetSymbolAddress((void**)&pb1, g_pb1);
    cudaGetSymbolAddress((void**)&pb2, g_pb2);
    cudaGetSymbolAddress((void**)&sx, g_sx);
    cudaGetSymbolAddress((void**)&sw, g_sw);
    cudaGetSymbolAddress((void**)&sq, g_sq);
    cudaGetSymbolAddress((void**)&sp, g_sp);
    cudaGetSymbolAddress((void**)&qf, g_q);
    cudaGetSymbolAddress((void**)&ptf, g_pt);

    quantize<<<MTOK, 256>>>(x, xa1, xa2, sx);
    quantize<<<NQKV, 256>>>(w_qkv, wb1, wb2, sw);
    gemm_i8<0><<<dim3(NQKV / 128, MTOK / 128), 256, SMEM_BYTES>>>(nullptr);
    kv_reduce<<<dim3(BB * HH, NSLICE), 256>>>();
    merge_m<<<BB * HH, 256>>>();
    make_p<<<dim3(EE / 64, HH, BB), 256>>>(w_o);
    quantize<<<MTOK, 256>>>(qf, qa1, qa2, sq);
    quantize<<<BB * EE, 256>>>(ptf, pb1, pb2, sp);
    gemm_i8<1><<<dim3(EE / 128, MTOK / 128), 256, SMEM_BYTES>>>(out);
}

// round 10
// speedup vs baseline: 1.5738x; 1.0508x over previous
#include <cuda_runtime.h>
#include <cstdint>
#include <cstddef>

// Problem constants
#define BB 4
#define SS 2048
#define EE 1024
#define HH 16
#define DD 64
#define MTOK (BB * SS)     // 8192
#define SCALE 0.125f

// int8 GEMM tiling
#define RSTR 80                         // bytes per smem row (64 data + 16 pad)
#define TILEB (128 * RSTR)              // 10240 B per limb tile
#define STAGEB (4 * TILEB)              // A1 A2 B1 B2
#define SMEM_BYTES (2 * STAGEB)         // 81920 B

// ---------------------------------------------------------------------------
// Scratch
// ---------------------------------------------------------------------------
__device__ float g_xtf[BB * EE * SS];          // X^T  [b][e][s]
__device__ float g_gf[BB * EE * EE];           // G_off = X^T X minus diag
__device__ float g_gd[BB * EE];                // diag(G)
__device__ float g_tf[BB * EE * EE];           // T = G Wv^T (+diag term)
__device__ float g_wqtf[EE * EE];              // Wq^T [e][j]
__device__ float g_wvtf[EE * EE];              // Wv^T [e][c]
__device__ float g_m[BB][HH][DD][DD];
__device__ float g_pt[BB][EE][EE];             // P^T [b][c][j]
__device__ float g_utf[BB * EE * EE];          // U^T [b][c][e]

__device__ unsigned char g_xa1[MTOK * EE], g_xa2[MTOK * EE];         // X rows
__device__ unsigned char g_xta1[BB * EE * SS], g_xta2[BB * EE * SS]; // X^T rows
__device__ unsigned char g_ga1[BB * EE * EE], g_ga2[BB * EE * EE];
__device__ unsigned char g_wv1[EE * EE], g_wv2[EE * EE];
__device__ unsigned char g_wqt1[EE * EE], g_wqt2[EE * EE];
__device__ unsigned char g_pta1[BB * EE * EE], g_pta2[BB * EE * EE];
__device__ unsigned char g_uta1[BB * EE * EE], g_uta2[BB * EE * EE];
__device__ float g_sx[MTOK], g_sxt[BB * EE], g_sg[BB * EE], g_swv[EE],
                 g_swqt[EE], g_spt[BB * EE], g_sut[BB * EE];

// ---------------------------------------------------------------------------
// Helpers
// ---------------------------------------------------------------------------
__device__ __forceinline__ uint32_t smem_u32(const void* p) {
    uint32_t a;
    asm("{ .reg .u64 t; cvta.to.shared.u64 t, %1; cvt.u32.u64 %0, t; }" : "=r"(a) : "l"(p));
    return a;
}
__device__ __forceinline__ void cpasync16(uint32_t s, const void* g) {
    asm volatile("cp.async.cg.shared.global [%0], [%1], 16;" :: "r"(s), "l"(g));
}
#define CP_COMMIT() asm volatile("cp.async.commit_group;" ::: "memory")
#define CP_WAIT(n)  asm volatile("cp.async.wait_group %0;" :: "n"(n) : "memory")

__device__ __forceinline__ void imma(int* c, const uint32_t* a, const uint32_t* b) {
    asm volatile(
        "mma.sync.aligned.m16n8k32.row.col.s32.s8.s8.s32 "
        "{%0,%1,%2,%3}, {%4,%5,%6,%7}, {%8,%9}, {%0,%1,%2,%3};"
        : "+r"(c[0]), "+r"(c[1]), "+r"(c[2]), "+r"(c[3])
        : "r"(a[0]), "r"(a[1]), "r"(a[2]), "r"(a[3]), "r"(b[0]), "r"(b[1]));
}

// ---------------------------------------------------------------------------
// quantize: rows of a [rows x len] fp32 matrix -> two s8 limbs + scale.
// len in {1024, 2048}. gatherV=1 remaps row -> w_qkv V-row.
// ---------------------------------------------------------------------------
__global__ __launch_bounds__(256) void quantize(const float* __restrict__ src,
                                                unsigned char* __restrict__ q1,
                                                unsigned char* __restrict__ q2,
                                                float* __restrict__ sdeq,
                                                int len, int gatherV) {
    const int row = blockIdx.x;
    const int srow = gatherV ? ((row >> 6) * 192 + 128 + (row & 63)) : row;
    const int tid = threadIdx.x;
    const int L = len >> 10;   // float4 groups per thread (1 or 2)
    const float4* p = (const float4*)(src + (size_t)srow * len);

    __shared__ float wmax[8];
    __shared__ float sinv;

    float4 v[2];
    float m = 0.0f;
    for (int i = 0; i < L; ++i) {
        v[i] = p[tid + i * 256];
        m = fmaxf(m, fmaxf(fmaxf(fabsf(v[i].x), fabsf(v[i].y)),
                           fmaxf(fabsf(v[i].z), fabsf(v[i].w))));
    }
#pragma unroll
    for (int o = 16; o > 0; o >>= 1) m = fmaxf(m, __shfl_xor_sync(0xFFFFFFFFu, m, o));
    if ((tid & 31) == 0) wmax[tid >> 5] = m;
    __syncthreads();
    if (tid == 0) {
        float mm = wmax[0];
#pragma unroll
        for (int i = 1; i < 8; ++i) mm = fmaxf(mm, wmax[i]);
        sdeq[row] = mm * (1.0f / 126.0f);
        sinv = (mm > 0.0f) ? 126.0f / mm : 0.0f;
    }
    __syncthreads();
    const float inv = sinv;

    for (int i = 0; i < L; ++i) {
        int a[4], b[4];
        float t, e;
        t = v[i].x * inv; a[0] = __float2int_rn(t); e = t - (float)a[0]; b[0] = __float2int_rn(e * 252.0f);
        t = v[i].y * inv; a[1] = __float2int_rn(t); e = t - (float)a[1]; b[1] = __float2int_rn(e * 252.0f);
        t = v[i].z * inv; a[2] = __float2int_rn(t); e = t - (float)a[2]; b[2] = __float2int_rn(e * 252.0f);
        t = v[i].w * inv; a[3] = __float2int_rn(t); e = t - (float)a[3]; b[3] = __float2int_rn(e * 252.0f);
        uint32_t p1 = (a[0] & 0xFF) | ((a[1] & 0xFF) << 8) | ((a[2] & 0xFF) << 16) | ((uint32_t)(a[3] & 0xFF) << 24);
        uint32_t p2 = (b[0] & 0xFF) | ((b[1] & 0xFF) << 8) | ((b[2] & 0xFF) << 16) | ((uint32_t)(b[3] & 0xFF) << 24);
        ((uint32_t*)q1)[(size_t)row * (len >> 2) + tid + i * 256] = p1;
        ((uint32_t*)q2)[(size_t)row * (len >> 2) + tid + i * 256] = p2;
    }
}

// ---------------------------------------------------------------------------
// transpose_x: X [b][s][e] -> g_xtf [b][e][s].  32x32 smem tiles.
// ---------------------------------------------------------------------------
__global__ __launch_bounds__(256) void transpose_x(const float* __restrict__ x) {
    __shared__ float t[32][33];
    const int e0 = blockIdx.x * 32, s0 = blockIdx.y * 32, b = blockIdx.z;
    const int c = threadIdx.x & 31, r0 = threadIdx.x >> 5;
#pragma unroll
    for (int p = 0; p < 4; ++p) {
        const int r = r0 + p * 8;
        t[r][c] = x[((size_t)b * SS + s0 + r) * EE + e0 + c];
    }
    __syncthreads();
#pragma unroll
    for (int p = 0; p < 4; ++p) {
        const int r = r0 + p * 8;
        g_xtf[((size_t)b * EE + e0 + r) * SS + s0 + c] = t[c][r];
    }
}

// ---------------------------------------------------------------------------
// transpose_w: gathered w_qkv rows -> dst[e][j].  off=0 -> Q rows, 128 -> V.
// ---------------------------------------------------------------------------
__global__ __launch_bounds__(256) void transpose_w(const float* __restrict__ w,
                                                   float* __restrict__ dst, int off) {
    __shared__ float t[32][33];
    const int e0 = blockIdx.x * 32, j0 = blockIdx.y * 32;
    const int c = threadIdx.x & 31, r0 = threadIdx.x >> 5;
#pragma unroll
    for (int p = 0; p < 4; ++p) {
        const int j = j0 + r0 + p * 8;
        const int srow = (j >> 6) * 192 + off + (j & 63);
        t[r0 + p * 8][c] = w[(size_t)srow * EE + e0 + c];
    }
    __syncthreads();
#pragma unroll
    for (int p = 0; p < 4; ++p) {
        const int r = r0 + p * 8;
        dst[(size_t)(e0 + r) * EE + j0 + c] = t[c][r];
    }
}

// ---------------------------------------------------------------------------
// int8 2-limb GEMM core — SINGLE instantiation, mode-parameterized at runtime.
// C tiles 128x128, 64-byte K chunks, 256 threads, 8 warps (warp tile 32x64).
// C = sA*sB*(P11 + Pmix/252).
// Operands: A rows at (z*aZ + bm), B rows at (z*bZ + bn), K-contig, depth kd.
// emode: 0 = G store (diag extracted), 1 = T store (+diag term),
//        2 = U^T store, 3 = final out (row = z*SS + local row).
// ---------------------------------------------------------------------------
__global__ __launch_bounds__(256, 1) void gemm_i8(
    const unsigned char* __restrict__ A1b, const unsigned char* __restrict__ A2b,
    const unsigned char* __restrict__ B1b, const unsigned char* __restrict__ B2b,
    const float* __restrict__ sAb, const float* __restrict__ sBb,
    float* __restrict__ Out, int kd, int aZ, int bZ, int emode) {
    extern __shared__ unsigned char smem[];
    const int tid = threadIdx.x;
    const int wid = tid >> 5, lane = tid & 31;
    const int g = lane >> 2, tg = lane & 3;
    const int warp_m = wid & 3;
    const int warp_n = wid >> 2;
    const int bn = blockIdx.x * 128;
    const int bm = blockIdx.y * 128;
    const int z = blockIdx.z;

    const unsigned char* A1 = A1b + (size_t)(z * aZ + bm) * kd;
    const unsigned char* A2 = A2b + (size_t)(z * aZ + bm) * kd;
    const unsigned char* B1 = B1b + (size_t)(z * bZ + bn) * kd;
    const unsigned char* B2 = B2b + (size_t)(z * bZ + bn) * kd;
    const float* sA = sAb + z * aZ + bm;
    const float* sB = sBb + z * bZ + bn;

    const uint32_t sb = smem_u32(smem);

    int acc11[2][8][4], accmx[2][8][4];
#pragma unroll
    for (int mt = 0; mt < 2; ++mt)
#pragma unroll
        for (int nt = 0; nt < 8; ++nt)
#pragma unroll
            for (int i = 0; i < 4; ++i) { acc11[mt][nt][i] = 0; accmx[mt][nt][i] = 0; }

    auto load_chunk = [&](int s, int k0) {
        const uint32_t base = sb + s * STAGEB;
#pragma unroll
        for (int it = 0; it < 2; ++it) {
            const int id = tid + it * 256;
            const int row = id >> 2;
            const int c16 = (id & 3) * 16;
            const uint32_t so = row * RSTR + c16;
            const size_t go = (size_t)row * kd + k0 + c16;
            cpasync16(base + so,              A1 + go);
            cpasync16(base + TILEB + so,      A2 + go);
            cpasync16(base + 2 * TILEB + so,  B1 + go);
            cpasync16(base + 3 * TILEB + so,  B2 + go);
        }
        CP_COMMIT();
    };

    load_chunk(0, 0);

    const int NK = kd >> 6;
    for (int kc = 0; kc < NK; ++kc) {
        const int s = kc & 1;
        if (kc + 1 < NK) {
            load_chunk(1 - s, (kc + 1) * 64);
            CP_WAIT(1);
        } else {
            CP_WAIT(0);
        }
        __syncthreads();

        const uint32_t stg = sb + s * STAGEB;
#pragma unroll
        for (int ks = 0; ks < 2; ++ks) {
            const uint32_t kof = ks * 32 + tg * 4;
            uint32_t a1f[2][4], a2f[2][4], b1f[8][2], b2f[8][2];
#pragma unroll
            for (int mt = 0; mt < 2; ++mt) {
                const uint32_t r0 = stg + (warp_m * 32 + mt * 16 + g) * RSTR + kof;
#pragma unroll
                for (int limb = 0; limb < 2; ++limb) {
                    uint32_t* f = limb ? a2f[mt] : a1f[mt];
                    const uint32_t rr = r0 + limb * TILEB;
                    asm volatile("ld.shared.b32 %0, [%1];" : "=r"(f[0]) : "r"(rr));
                    asm volatile("ld.shared.b32 %0, [%1];" : "=r"(f[1]) : "r"(rr + 8 * RSTR));
                    asm volatile("ld.shared.b32 %0, [%1];" : "=r"(f[2]) : "r"(rr + 16));
                    asm volatile("ld.shared.b32 %0, [%1];" : "=r"(f[3]) : "r"(rr + 8 * RSTR + 16));
                }
            }
#pragma unroll
            for (int nt = 0; nt < 8; ++nt) {
                const uint32_t r0 = stg + 2 * TILEB + (warp_n * 64 + nt * 8 + g) * RSTR + kof;
                asm volatile("ld.shared.b32 %0, [%1];" : "=r"(b1f[nt][0]) : "r"(r0));
                asm volatile("ld.shared.b32 %0, [%1];" : "=r"(b1f[nt][1]) : "r"(r0 + 16));
                asm volatile("ld.shared.b32 %0, [%1];" : "=r"(b2f[nt][0]) : "r"(r0 + TILEB));
                asm volatile("ld.shared.b32 %0, [%1];" : "=r"(b2f[nt][1]) : "r"(r0 + TILEB + 16));
            }
#pragma unroll
            for (int mt = 0; mt < 2; ++mt)
#pragma unroll
                for (int nt = 0; nt < 8; ++nt) imma(acc11[mt][nt], a1f[mt], b1f[nt]);
#pragma unroll
            for (int mt = 0; mt < 2; ++mt)
#pragma unroll
                for (int nt = 0; nt < 8; ++nt) imma(accmx[mt][nt], a1f[mt], b2f[nt]);
#pragma unroll
            for (int mt = 0; mt < 2; ++mt)
#pragma unroll
                for (int nt = 0; nt < 8; ++nt) imma(accmx[mt][nt], a2f[mt], b1f[nt]);
        }
        __syncthreads();
    }

    // Epilogue: dequant + runtime-mode store (all coalesced float2).
#pragma unroll
    for (int mt = 0; mt < 2; ++mt) {
        const int rb = warp_m * 32 + mt * 16 + g;
        const float sa0 = sA[rb], sa1 = sA[rb + 8];
#pragma unroll
        for (int nt = 0; nt < 8; ++nt) {
            const int coff = warp_n * 64 + nt * 8 + 2 * tg;
            const float sb0 = sB[coff], sb1 = sB[coff + 1];
            const int col = bn + coff;
#pragma unroll
            for (int half = 0; half < 2; ++half) {
                const int rl = bm + rb + half * 8;          // row within batch z
                const float sa = half ? sa1 : sa0;
                float v0 = ((float)acc11[mt][nt][half * 2 + 0]
                            + (float)accmx[mt][nt][half * 2 + 0] * (1.0f / 252.0f)) * sa * sb0;
                float v1 = ((float)acc11[mt][nt][half * 2 + 1]
                            + (float)accmx[mt][nt][half * 2 + 1] * (1.0f / 252.0f)) * sa * sb1;
                if (emode == 0) {
                    if (rl == col)     { g_gd[z * EE + rl] = v0; v0 = 0.0f; }
                    if (rl == col + 1) { g_gd[z * EE + rl] = v1; v1 = 0.0f; }
                    *(float2*)&g_gf[((size_t)z * EE + rl) * EE + col] = make_float2(v0, v1);
                } else if (emode == 1) {
                    const float gd = g_gd[z * EE + rl];
                    const float2 wv = *(const float2*)&g_wvtf[(size_t)rl * EE + col];
                    v0 += gd * wv.x;
                    v1 += gd * wv.y;
                    *(float2*)&g_tf[((size_t)z * EE + rl) * EE + col] = make_float2(v0, v1);
                } else if (emode == 2) {
                    *(float2*)&g_utf[((size_t)z * EE + rl) * EE + col] = make_float2(v0, v1);
                } else {
                    *(float2*)&Out[((size_t)z * SS + rl) * EE + col] = make_float2(v0, v1);
                }
            }
        }
    }
}

// ---------------------------------------------------------------------------
// mstep: M[b][h] = SCALE * Wk_h @ T[b][:, h*64:(h+1)*64]
// ---------------------------------------------------------------------------
__global__ __launch_bounds__(256) void mstep(const float* __restrict__ w) {
    const int bh = blockIdx.x;
    const int b = bh / HH, h = bh % HH;
    const int tid = threadIdx.x;
    const int tx = tid & 15;   // d2
    const int ty = tid >> 4;   // d1

    __shared__ float Wks[32][68];   // [e][d1]
    __shared__ float Ts[32][64];    // [e][d2]

    float acc[4][4];
#pragma unroll
    for (int i = 0; i < 4; ++i)
#pragma unroll
        for (int j = 0; j < 4; ++j) acc[i][j] = 0.0f;

    for (int e0 = 0; e0 < EE; e0 += 32) {
#pragma unroll
        for (int it = 0; it < 2; ++it) {
            const int fid = tid + it * 256;
            const int d1 = fid >> 3;
            const int c4 = (fid & 7) * 4;
            float4 v = *(const float4*)&w[(size_t)(h * 192 + 64 + d1) * EE + e0 + c4];
            Wks[c4 + 0][d1] = v.x; Wks[c4 + 1][d1] = v.y;
            Wks[c4 + 2][d1] = v.z; Wks[c4 + 3][d1] = v.w;
        }
#pragma unroll
        for (int it = 0; it < 2; ++it) {
            const int fid = tid + it * 256;
            const int r = fid >> 4;
            const int c4 = (fid & 15) * 4;
            *(float4*)&Ts[r][c4] =
                *(const float4*)&g_tf[((size_t)b * EE + e0 + r) * EE + h * 64 + c4];
        }
        __syncthreads();
#pragma unroll 8
        for (int e = 0; e < 32; ++e) {
            float a[4], bb[4];
#pragma unroll
            for (int i = 0; i < 4; ++i) a[i] = Wks[e][ty * 4 + i];
#pragma unroll
            for (int j = 0; j < 4; ++j) bb[j] = Ts[e][tx * 4 + j];
#pragma unroll
            for (int i = 0; i < 4; ++i)
#pragma unroll
                for (int j = 0; j < 4; ++j) acc[i][j] += a[i] * bb[j];
        }
        __syncthreads();
    }
#pragma unroll
    for (int i = 0; i < 4; ++i)
#pragma unroll
        for (int j = 0; j < 4; ++j)
            g_m[b][h][ty * 4 + i][tx * 4 + j] = SCALE * acc[i][j];
}

// ---------------------------------------------------------------------------
// make_p: g_pt[b][c][r] = sum_d M[b][h][rl][d] * w_o[c][h*64+d]  (r = h*64+rl)
// ---------------------------------------------------------------------------
__global__ __launch_bounds__(256) void make_p(const float* __restrict__ w_o) {
    const int h = blockIdx.y;
    const int b = blockIdx.z;
    const int c0 = blockIdx.x * 64;
    const int tid = threadIdx.x;
    const int tx = tid & 15;   // rl
    const int ty = tid >> 4;   // c

    __shared__ float Wost[64][68];   // [d][c]
    __shared__ float Mst[64][68];    // [d][rl]

#pragma unroll
    for (int it = 0; it < 4; ++it) {
        const int fid = tid + it * 256;
        const int c = fid >> 4;
        const int d4 = (fid & 15) * 4;
        float4 v = *(const float4*)&w_o[(size_t)(c0 + c) * EE + h * 64 + d4];
        Wost[d4 + 0][c] = v.x; Wost[d4 + 1][c] = v.y;
        Wost[d4 + 2][c] = v.z; Wost[d4 + 3][c] = v.w;
        float4 m = *(const float4*)&g_m[b][h][c][d4];
        Mst[d4 + 0][c] = m.x; Mst[d4 + 1][c] = m.y;
        Mst[d4 + 2][c] = m.z; Mst[d4 + 3][c] = m.w;
    }
    __syncthreads();

    float acc[4][4];
#pragma unroll
    for (int i = 0; i < 4; ++i)
#pragma unroll
        for (int j = 0; j < 4; ++j) acc[i][j] = 0.0f;
#pragma unroll 8
    for (int d = 0; d < 64; ++d) {
        float a[4], bb[4];
#pragma unroll
        for (int i = 0; i < 4; ++i) a[i] = Wost[d][ty * 4 + i];
#pragma unroll
        for (int j = 0; j < 4; ++j) bb[j] = Mst[d][tx * 4 + j];
#pragma unroll
        for (int i = 0; i < 4; ++i)
#pragma unroll
            for (int j = 0; j < 4; ++j) acc[i][j] += a[i] * bb[j];
    }
#pragma unroll
    for (int i = 0; i < 4; ++i) {
        float4 v;
        v.x = acc[i][0]; v.y = acc[i][1]; v.z = acc[i][2]; v.w = acc[i][3];
        *(float4*)&g_pt[b][c0 + ty * 4 + i][h * 64 + tx * 4] = v;
    }
}

// ---------------------------------------------------------------------------
// Launch
// ---------------------------------------------------------------------------
extern "C" void kernel_launch(void* const* d_in, const int* in_sizes, int n_in,
                              void* d_out, int out_size) {
    const float* x = (const float*)d_in[0];
    const float* w_qkv = (const float*)d_in[1];
    const float* w_o = (const float*)d_in[2];
    float* out = (float*)d_out;

    cudaFuncSetAttribute(gemm_i8, cudaFuncAttributeMaxDynamicSharedMemorySize, SMEM_BYTES);

    unsigned char *xa1, *xa2, *xta1, *xta2, *ga1, *ga2, *wv1, *wv2, *wqt1, *wqt2,
                  *pta1, *pta2, *uta1, *uta2;
    float *sx, *sxt, *sg, *swv, *swqt, *spt, *sut, *xtf, *gf, *wqtf, *wvtf, *ptf, *utf;
    cudaGetSymbolAddress((void**)&xa1, g_xa1);   cudaGetSymbolAddress((void**)&xa2, g_xa2);
    cudaGetSymbolAddress((void**)&xta1, g_xta1); cudaGetSymbolAddress((void**)&xta2, g_xta2);
    cudaGetSymbolAddress((void**)&ga1, g_ga1);   cudaGetSymbolAddress((void**)&ga2, g_ga2);
    cudaGetSymbolAddress((void**)&wv1, g_wv1);   cudaGetSymbolAddress((void**)&wv2, g_wv2);
    cudaGetSymbolAddress((void**)&wqt1, g_wqt1); cudaGetSymbolAddress((void**)&wqt2, g_wqt2);
    cudaGetSymbolAddress((void**)&pta1, g_pta1); cudaGetSymbolAddress((void**)&pta2, g_pta2);
    cudaGetSymbolAddress((void**)&uta1, g_uta1); cudaGetSymbolAddress((void**)&uta2, g_uta2);
    cudaGetSymbolAddress((void**)&sx, g_sx);     cudaGetSymbolAddress((void**)&sxt, g_sxt);
    cudaGetSymbolAddress((void**)&sg, g_sg);     cudaGetSymbolAddress((void**)&swv, g_swv);
    cudaGetSymbolAddress((void**)&swqt, g_swqt); cudaGetSymbolAddress((void**)&spt, g_spt);
    cudaGetSymbolAddress((void**)&sut, g_sut);
    cudaGetSymbolAddress((void**)&xtf, g_xtf);   cudaGetSymbolAddress((void**)&gf, g_gf);
    cudaGetSymbolAddress((void**)&wqtf, g_wqtf); cudaGetSymbolAddress((void**)&wvtf, g_wvtf);
    cudaGetSymbolAddress((void**)&ptf, g_pt);    cudaGetSymbolAddress((void**)&utf, g_utf);

    // Stage 0: transposes + input quantization
    transpose_x<<<dim3(EE / 32, SS / 32, BB), 256>>>(x);
    transpose_w<<<dim3(32, 32), 256>>>(w_qkv, wqtf, 0);
    transpose_w<<<dim3(32, 32), 256>>>(w_qkv, wvtf, 128);
    quantize<<<BB * EE, 256>>>(xtf, xta1, xta2, sxt, SS, 0);
    quantize<<<MTOK, 256>>>(x, xa1, xa2, sx, EE, 0);
    quantize<<<EE, 256>>>(w_qkv, wv1, wv2, swv, EE, 1);     // V rows gathered
    quantize<<<EE, 256>>>(wqtf, wqt1, wqt2, swqt, EE, 0);

    // Stage 1: G = X^T X per batch (diag extracted)
    gemm_i8<<<dim3(8, 8, BB), 256, SMEM_BYTES>>>(
        xta1, xta2, xta1, xta2, sxt, sxt, nullptr, 2048, EE, EE, 0);
    quantize<<<BB * EE, 256>>>(gf, ga1, ga2, sg, EE, 0);

    // Stage 2: T = G Wv^T (+ diag term), M = SCALE * Wk T
    gemm_i8<<<dim3(8, 8, BB), 256, SMEM_BYTES>>>(
        ga1, ga2, wv1, wv2, sg, swv, nullptr, 1024, EE, 0, 1);
    mstep<<<BB * HH, 256>>>(w_qkv);

    // Stage 3: P^T, U^T = P^T Wq
    make_p<<<dim3(EE / 64, HH, BB), 256>>>(w_o);
    quantize<<<BB * EE, 256>>>(ptf, pta1, pta2, spt, EE, 0);
    gemm_i8<<<dim3(8, 8, BB), 256, SMEM_BYTES>>>(
        pta1, pta2, wqt1, wqt2, spt, swqt, nullptr, 1024, EE, 0, 2);
    quantize<<<BB * EE, 256>>>(utf, uta1, uta2, sut, EE, 0);

    // Stage 4: out = X U  (rows per batch = SS)
    gemm_i8<<<dim3(8, SS / 128, BB), 256, SMEM_BYTES>>>(
        xa1, xa2, uta1, uta2, sx, sut, out, 1024, SS, EE, 3);
}

// round 12
// speedup vs baseline: 1.6809x; 1.0680x over previous
#include <cuda_runtime.h>
#include <cstdint>
#include <cstddef>

// Problem constants
#define BB 4
#define SS 2048
#define EE 1024
#define HH 16
#define DD 64
#define MTOK (BB * SS)     // 8192
#define SCALE 0.125f

// int8 GEMM tiling
#define RSTR 80                         // bytes per smem row (64 data + 16 pad)
#define TILEB (128 * RSTR)              // 10240 B per limb tile
#define STAGEB (4 * TILEB)              // A1 A2 B1 B2
#define SMEM_BYTES (2 * STAGEB)         // 81920 B

// Triangular block decode tables for the symmetric G GEMM (36 upper blocks).
__constant__ unsigned char c_tri_i[36] = {
    0,0,0,0,0,0,0,0, 1,1,1,1,1,1,1, 2,2,2,2,2,2, 3,3,3,3,3, 4,4,4,4, 5,5,5, 6,6, 7};
__constant__ unsigned char c_tri_j[36] = {
    0,1,2,3,4,5,6,7, 1,2,3,4,5,6,7, 2,3,4,5,6,7, 3,4,5,6,7, 4,5,6,7, 5,6,7, 6,7, 7};

// ---------------------------------------------------------------------------
// Scratch
// ---------------------------------------------------------------------------
__device__ float g_xtf[BB * EE * SS];          // X^T  [b][e][s]
__device__ float g_gf[BB * EE * EE];           // G_off = X^T X minus diag
__device__ float g_gd[BB * EE];                // diag(G)
__device__ float g_tf[BB * EE * EE];           // T = G Wv^T (+diag term)
__device__ float g_wqtf[EE * EE];              // Wq^T [e][j]
__device__ float g_wvtf[EE * EE];              // Wv^T [e][c]
__device__ float g_pt[BB][EE][EE];             // P^T [b][c][j]
__device__ float g_utf[BB * EE * EE];          // U^T [b][c][e]

__device__ unsigned char g_xa1[MTOK * EE], g_xa2[MTOK * EE];         // X rows
__device__ unsigned char g_xta1[BB * EE * SS], g_xta2[BB * EE * SS]; // X^T rows
__device__ unsigned char g_ga1[BB * EE * EE], g_ga2[BB * EE * EE];
__device__ unsigned char g_wv1[EE * EE], g_wv2[EE * EE];
__device__ unsigned char g_wqt1[EE * EE], g_wqt2[EE * EE];
__device__ unsigned char g_pta1[BB * EE * EE], g_pta2[BB * EE * EE];
__device__ unsigned char g_uta1[BB * EE * EE], g_uta2[BB * EE * EE];
__device__ float g_sx[MTOK], g_sxt[BB * EE], g_sg[BB * EE], g_swv[EE],
                 g_swqt[EE], g_spt[BB * EE], g_sut[BB * EE];

// ---------------------------------------------------------------------------
// Helpers
// ---------------------------------------------------------------------------
__device__ __forceinline__ uint32_t smem_u32(const void* p) {
    uint32_t a;
    asm("{ .reg .u64 t; cvta.to.shared.u64 t, %1; cvt.u32.u64 %0, t; }" : "=r"(a) : "l"(p));
    return a;
}
__device__ __forceinline__ void cpasync16(uint32_t s, const void* g) {
    asm volatile("cp.async.cg.shared.global [%0], [%1], 16;" :: "r"(s), "l"(g));
}
#define CP_COMMIT() asm volatile("cp.async.commit_group;" ::: "memory")
#define CP_WAIT(n)  asm volatile("cp.async.wait_group %0;" :: "n"(n) : "memory")

__device__ __forceinline__ void imma(int* c, const uint32_t* a, const uint32_t* b) {
    asm volatile(
        "mma.sync.aligned.m16n8k32.row.col.s32.s8.s8.s32 "
        "{%0,%1,%2,%3}, {%4,%5,%6,%7}, {%8,%9}, {%0,%1,%2,%3};"
        : "+r"(c[0]), "+r"(c[1]), "+r"(c[2]), "+r"(c[3])
        : "r"(a[0]), "r"(a[1]), "r"(a[2]), "r"(a[3]), "r"(b[0]), "r"(b[1]));
}

// ---------------------------------------------------------------------------
// quant_row_256: one 256-thread block quantizes one fp32 row of length len
// (1024 or 2048) into two s8 limbs + scale.
// ---------------------------------------------------------------------------
__device__ __forceinline__ void quant_row_256(const float* __restrict__ src,
                                              unsigned char* __restrict__ q1,
                                              unsigned char* __restrict__ q2,
                                              float* __restrict__ sdeq, int len) {
    const int tid = threadIdx.x;
    const int L = len >> 10;
    const float4* p = (const float4*)src;

    __shared__ float wmax[8];
    __shared__ float sinv;

    float4 v[2];
    float m = 0.0f;
    for (int i = 0; i < L; ++i) {
        v[i] = p[tid + i * 256];
        m = fmaxf(m, fmaxf(fmaxf(fabsf(v[i].x), fabsf(v[i].y)),
                           fmaxf(fabsf(v[i].z), fabsf(v[i].w))));
    }
#pragma unroll
    for (int o = 16; o > 0; o >>= 1) m = fmaxf(m, __shfl_xor_sync(0xFFFFFFFFu, m, o));
    if ((tid & 31) == 0) wmax[tid >> 5] = m;
    __syncthreads();
    if (tid == 0) {
        float mm = wmax[0];
#pragma unroll
        for (int i = 1; i < 8; ++i) mm = fmaxf(mm, wmax[i]);
        *sdeq = mm * (1.0f / 126.0f);
        sinv = (mm > 0.0f) ? 126.0f / mm : 0.0f;
    }
    __syncthreads();
    const float inv = sinv;

    for (int i = 0; i < L; ++i) {
        int a[4], b[4];
        float t, e;
        t = v[i].x * inv; a[0] = __float2int_rn(t); e = t - (float)a[0]; b[0] = __float2int_rn(e * 252.0f);
        t = v[i].y * inv; a[1] = __float2int_rn(t); e = t - (float)a[1]; b[1] = __float2int_rn(e * 252.0f);
        t = v[i].z * inv; a[2] = __float2int_rn(t); e = t - (float)a[2]; b[2] = __float2int_rn(e * 252.0f);
        t = v[i].w * inv; a[3] = __float2int_rn(t); e = t - (float)a[3]; b[3] = __float2int_rn(e * 252.0f);
        uint32_t p1 = (a[0] & 0xFF) | ((a[1] & 0xFF) << 8) | ((a[2] & 0xFF) << 16) | ((uint32_t)(a[3] & 0xFF) << 24);
        uint32_t p2 = (b[0] & 0xFF) | ((b[1] & 0xFF) << 8) | ((b[2] & 0xFF) << 16) | ((uint32_t)(b[3] & 0xFF) << 24);
        ((uint32_t*)q1)[tid + i * 256] = p1;
        ((uint32_t*)q2)[tid + i * 256] = p2;
    }
}

// Generic single-source quantize (G / Pt / Ut stages).
__global__ __launch_bounds__(256) void quantize(const float* __restrict__ src,
                                                unsigned char* __restrict__ q1,
                                                unsigned char* __restrict__ q2,
                                                float* __restrict__ sdeq, int len) {
    const int row = blockIdx.x;
    quant_row_256(src + (size_t)row * len, q1 + (size_t)row * len,
                  q2 + (size_t)row * len, sdeq + row, len);
}

// Fused stage-0 quantize: X^T rows, X rows, Wv rows (gathered), Wq^T rows.
__global__ __launch_bounds__(256) void quant_all(const float* __restrict__ x,
                                                 const float* __restrict__ w) {
    const int bid = blockIdx.x;
    if (bid < BB * EE) {                      // X^T rows, len 2048
        quant_row_256(g_xtf + (size_t)bid * SS, g_xta1 + (size_t)bid * SS,
                      g_xta2 + (size_t)bid * SS, g_sxt + bid, SS);
    } else if (bid < BB * EE + MTOK) {        // X rows, len 1024
        const int r = bid - BB * EE;
        quant_row_256(x + (size_t)r * EE, g_xa1 + (size_t)r * EE,
                      g_xa2 + (size_t)r * EE, g_sx + r, EE);
    } else if (bid < BB * EE + MTOK + EE) {   // Wv rows gathered from w_qkv
        const int r = bid - BB * EE - MTOK;
        const int sr = (r >> 6) * 192 + 128 + (r & 63);
        quant_row_256(w + (size_t)sr * EE, g_wv1 + (size_t)r * EE,
                      g_wv2 + (size_t)r * EE, g_swv + r, EE);
    } else {                                  // Wq^T rows
        const int r = bid - BB * EE - MTOK - EE;
        quant_row_256(g_wqtf + (size_t)r * EE, g_wqt1 + (size_t)r * EE,
                      g_wqt2 + (size_t)r * EE, g_swqt + r, EE);
    }
}

// ---------------------------------------------------------------------------
// prep_t: fused transposes.  bid < 8192: X -> X^T tile; else Wq/Wv gather+T.
// ---------------------------------------------------------------------------
__global__ __launch_bounds__(256) void prep_t(const float* __restrict__ x,
                                              const float* __restrict__ w) {
    __shared__ float t[32][33];
    const int bid = blockIdx.x;
    const int c = threadIdx.x & 31, r0 = threadIdx.x >> 5;

    if (bid < 8192) {
        const int e0 = (bid & 31) * 32;
        const int s0 = ((bid >> 5) & 63) * 32;
        const int b = bid >> 11;
#pragma unroll
        for (int p = 0; p < 4; ++p) {
            const int r = r0 + p * 8;
            t[r][c] = x[((size_t)b * SS + s0 + r) * EE + e0 + c];
        }
        __syncthreads();
#pragma unroll
        for (int p = 0; p < 4; ++p) {
            const int r = r0 + p * 8;
            g_xtf[((size_t)b * EE + e0 + r) * SS + s0 + c] = t[c][r];
        }
    } else {
        const int tt = bid - 8192;
        const int which = tt >> 10;           // 0 -> Wq^T, 1 -> Wv^T
        const int rem = tt & 1023;
        const int e0 = (rem & 31) * 32;
        const int j0 = (rem >> 5) * 32;
        const int off = which ? 128 : 0;
        float* dst = which ? g_wvtf : g_wqtf;
#pragma unroll
        for (int p = 0; p < 4; ++p) {
            const int j = j0 + r0 + p * 8;
            const int srow = (j >> 6) * 192 + off + (j & 63);
            t[r0 + p * 8][c] = w[(size_t)srow * EE + e0 + c];
        }
        __syncthreads();
#pragma unroll
        for (int p = 0; p < 4; ++p) {
            const int r = r0 + p * 8;
            dst[(size_t)(e0 + r) * EE + j0 + c] = t[c][r];
        }
    }
}

// ---------------------------------------------------------------------------
// int8 2-limb GEMM core — single instantiation, mode-parameterized.
// emode 0: G = XT@XT^T, TRIANGULAR grid (36 upper blocks via const LUT),
//          diag extracted, off-diag blocks mirrored.  kd=2048.
// emode 1: T = G@Wv^T + diag term.  emode 2: U^T = Pt@WqT^T.
// emode 3: out = X@U (row = z*SS + local).
// ---------------------------------------------------------------------------
__global__ __launch_bounds__(256, 1) void gemm_i8(
    const unsigned char* __restrict__ A1b, const unsigned char* __restrict__ A2b,
    const unsigned char* __restrict__ B1b, const unsigned char* __restrict__ B2b,
    const float* __restrict__ sAb, const float* __restrict__ sBb,
    float* __restrict__ Out, int kd, int aZ, int bZ, int emode) {
    extern __shared__ unsigned char smem[];
    const int tid = threadIdx.x;
    const int wid = tid >> 5, lane = tid & 31;
    const int g = lane >> 2, tg = lane & 3;
    const int warp_m = wid & 3;
    const int warp_n = wid >> 2;
    const int z = blockIdx.z;

    int bm, bn;
    if (emode == 0) {
        bm = (int)c_tri_i[blockIdx.x] * 128;
        bn = (int)c_tri_j[blockIdx.x] * 128;
    } else {
        bn = blockIdx.x * 128;
        bm = blockIdx.y * 128;
    }

    const unsigned char* A1 = A1b + (size_t)(z * aZ + bm) * kd;
    const unsigned char* A2 = A2b + (size_t)(z * aZ + bm) * kd;
    const unsigned char* B1 = B1b + (size_t)(z * bZ + bn) * kd;
    const unsigned char* B2 = B2b + (size_t)(z * bZ + bn) * kd;
    const float* sA = sAb + z * aZ + bm;
    const float* sB = sBb + z * bZ + bn;

    const uint32_t sb = smem_u32(smem);

    int acc11[2][8][4], accmx[2][8][4];
#pragma unroll
    for (int mt = 0; mt < 2; ++mt)
#pragma unroll
        for (int nt = 0; nt < 8; ++nt)
#pragma unroll
            for (int i = 0; i < 4; ++i) { acc11[mt][nt][i] = 0; accmx[mt][nt][i] = 0; }

    auto load_chunk = [&](int s, int k0) {
        const uint32_t base = sb + s * STAGEB;
#pragma unroll
        for (int it = 0; it < 2; ++it) {
            const int id = tid + it * 256;
            const int row = id >> 2;
            const int c16 = (id & 3) * 16;
            const uint32_t so = row * RSTR + c16;
            const size_t go = (size_t)row * kd + k0 + c16;
            cpasync16(base + so,              A1 + go);
            cpasync16(base + TILEB + so,      A2 + go);
            cpasync16(base + 2 * TILEB + so,  B1 + go);
            cpasync16(base + 3 * TILEB + so,  B2 + go);
        }
        CP_COMMIT();
    };

    load_chunk(0, 0);

    const int NK = kd >> 6;
    for (int kc = 0; kc < NK; ++kc) {
        const int s = kc & 1;
        if (kc + 1 < NK) {
            load_chunk(1 - s, (kc + 1) * 64);
            CP_WAIT(1);
        } else {
            CP_WAIT(0);
        }
        __syncthreads();

        const uint32_t stg = sb + s * STAGEB;
#pragma unroll
        for (int ks = 0; ks < 2; ++ks) {
            const uint32_t kof = ks * 32 + tg * 4;
            uint32_t a1f[2][4], a2f[2][4], b1f[8][2], b2f[8][2];
#pragma unroll
            for (int mt = 0; mt < 2; ++mt) {
                const uint32_t r0 = stg + (warp_m * 32 + mt * 16 + g) * RSTR + kof;
#pragma unroll
                for (int limb = 0; limb < 2; ++limb) {
                    uint32_t* f = limb ? a2f[mt] : a1f[mt];
                    const uint32_t rr = r0 + limb * TILEB;
                    asm volatile("ld.shared.b32 %0, [%1];" : "=r"(f[0]) : "r"(rr));
                    asm volatile("ld.shared.b32 %0, [%1];" : "=r"(f[1]) : "r"(rr + 8 * RSTR));
                    asm volatile("ld.shared.b32 %0, [%1];" : "=r"(f[2]) : "r"(rr + 16));
                    asm volatile("ld.shared.b32 %0, [%1];" : "=r"(f[3]) : "r"(rr + 8 * RSTR + 16));
                }
            }
#pragma unroll
            for (int nt = 0; nt < 8; ++nt) {
                const uint32_t r0 = stg + 2 * TILEB + (warp_n * 64 + nt * 8 + g) * RSTR + kof;
                asm volatile("ld.shared.b32 %0, [%1];" : "=r"(b1f[nt][0]) : "r"(r0));
                asm volatile("ld.shared.b32 %0, [%1];" : "=r"(b1f[nt][1]) : "r"(r0 + 16));
                asm volatile("ld.shared.b32 %0, [%1];" : "=r"(b2f[nt][0]) : "r"(r0 + TILEB));
                asm volatile("ld.shared.b32 %0, [%1];" : "=r"(b2f[nt][1]) : "r"(r0 + TILEB + 16));
            }
#pragma unroll
            for (int mt = 0; mt < 2; ++mt)
#pragma unroll
                for (int nt = 0; nt < 8; ++nt) imma(acc11[mt][nt], a1f[mt], b1f[nt]);
#pragma unroll
            for (int mt = 0; mt < 2; ++mt)
#pragma unroll
                for (int nt = 0; nt < 8; ++nt) imma(accmx[mt][nt], a1f[mt], b2f[nt]);
#pragma unroll
            for (int mt = 0; mt < 2; ++mt)
#pragma unroll
                for (int nt = 0; nt < 8; ++nt) imma(accmx[mt][nt], a2f[mt], b1f[nt]);
        }
        __syncthreads();
    }

    // Epilogue: dequant + runtime-mode store.
#pragma unroll
    for (int mt = 0; mt < 2; ++mt) {
        const int rb = warp_m * 32 + mt * 16 + g;
        const float sa0 = sA[rb], sa1 = sA[rb + 8];
#pragma unroll
        for (int nt = 0; nt < 8; ++nt) {
            const int coff = warp_n * 64 + nt * 8 + 2 * tg;
            const float sb0 = sB[coff], sb1 = sB[coff + 1];
            const int col = bn + coff;
#pragma unroll
            for (int half = 0; half < 2; ++half) {
                const int rl = bm + rb + half * 8;
                const float sa = half ? sa1 : sa0;
                float v0 = ((float)acc11[mt][nt][half * 2 + 0]
                            + (float)accmx[mt][nt][half * 2 + 0] * (1.0f / 252.0f)) * sa * sb0;
                float v1 = ((float)acc11[mt][nt][half * 2 + 1]
                            + (float)accmx[mt][nt][half * 2 + 1] * (1.0f / 252.0f)) * sa * sb1;
                if (emode == 0) {
                    if (rl == col)     { g_gd[z * EE + rl] = v0; v0 = 0.0f; }
                    if (rl == col + 1) { g_gd[z * EE + rl] = v1; v1 = 0.0f; }
                    *(float2*)&g_gf[((size_t)z * EE + rl) * EE + col] = make_float2(v0, v1);
                    if (bm != bn) {   // mirror into lower triangle (exact copy)
                        g_gf[((size_t)z * EE + col) * EE + rl] = v0;
                        g_gf[((size_t)z * EE + col + 1) * EE + rl] = v1;
                    }
                } else if (emode == 1) {
                    const float gd = g_gd[z * EE + rl];
                    const float2 wv = *(const float2*)&g_wvtf[(size_t)rl * EE + col];
                    v0 += gd * wv.x;
                    v1 += gd * wv.y;
                    *(float2*)&g_tf[((size_t)z * EE + rl) * EE + col] = make_float2(v0, v1);
                } else if (emode == 2) {
                    *(float2*)&g_utf[((size_t)z * EE + rl) * EE + col] = make_float2(v0, v1);
                } else {
                    *(float2*)&Out[((size_t)z * SS + rl) * EE + col] = make_float2(v0, v1);
                }
            }
        }
    }
}

// ---------------------------------------------------------------------------
// heads: fused mstep + make_p.  Grid (HH, BB), 256 threads.
// Phase 1: M = SCALE * Wk_h @ T[b][:, h*64:]   (kept in smem, d-major)
// Phase 2: P^T[b][c][h*64+rl] = sum_d M[rl][d] * w_o[c][h*64+d], all c tiles.
// ---------------------------------------------------------------------------
__global__ __launch_bounds__(256) void heads(const float* __restrict__ w,
                                             const float* __restrict__ w_o) {
    const int h = blockIdx.x, b = blockIdx.y;
    const int tid = threadIdx.x;
    const int tx = tid & 15;
    const int ty = tid >> 4;

    __shared__ float Msh[64][68];   // [d][rl] = M[rl][d], persists
    __shared__ float buf[64][68];   // phase1: rows 0-31 Wk^T, 32-63 T; phase2: Wo^T

    // Phase 1
    float acc[4][4];
#pragma unroll
    for (int i = 0; i < 4; ++i)
#pragma unroll
        for (int j = 0; j < 4; ++j) acc[i][j] = 0.0f;

    for (int e0 = 0; e0 < EE; e0 += 32) {
#pragma unroll
        for (int it = 0; it < 2; ++it) {
            const int fid = tid + it * 256;
            const int d1 = fid >> 3;
            const int c4 = (fid & 7) * 4;
            float4 v = *(const float4*)&w[(size_t)(h * 192 + 64 + d1) * EE + e0 + c4];
            buf[c4 + 0][d1] = v.x; buf[c4 + 1][d1] = v.y;
            buf[c4 + 2][d1] = v.z; buf[c4 + 3][d1] = v.w;
        }
#pragma unroll
        for (int it = 0; it < 2; ++it) {
            const int fid = tid + it * 256;
            const int r = fid >> 4;
            const int c4 = (fid & 15) * 4;
            *(float4*)&buf[32 + r][c4] =
                *(const float4*)&g_tf[((size_t)b * EE + e0 + r) * EE + h * 64 + c4];
        }
        __syncthreads();
#pragma unroll 8
        for (int e = 0; e < 32; ++e) {
            float a[4], bb[4];
#pragma unroll
            for (int i = 0; i < 4; ++i) a[i] = buf[e][ty * 4 + i];
#pragma unroll
            for (int j = 0; j < 4; ++j) bb[j] = buf[32 + e][tx * 4 + j];
#pragma unroll
            for (int i = 0; i < 4; ++i)
#pragma unroll
                for (int j = 0; j < 4; ++j) acc[i][j] += a[i] * bb[j];
        }
        __syncthreads();
    }
#pragma unroll
    for (int i = 0; i < 4; ++i)
#pragma unroll
        for (int j = 0; j < 4; ++j)
            Msh[tx * 4 + j][ty * 4 + i] = SCALE * acc[i][j];
    __syncthreads();

    // Phase 2: tx -> rl, ty -> c
    for (int c0 = 0; c0 < EE; c0 += 64) {
#pragma unroll
        for (int it = 0; it < 4; ++it) {
            const int fid = tid + it * 256;
            const int c = fid >> 4;
            const int d4 = (fid & 15) * 4;
            float4 v = *(const float4*)&w_o[(size_t)(c0 + c) * EE + h * 64 + d4];
            buf[d4 + 0][c] = v.x; buf[d4 + 1][c] = v.y;
            buf[d4 + 2][c] = v.z; buf[d4 + 3][c] = v.w;
        }
        __syncthreads();

        float a2[4][4];
#pragma unroll
        for (int i = 0; i < 4; ++i)
#pragma unroll
            for (int j = 0; j < 4; ++j) a2[i][j] = 0.0f;
#pragma unroll 8
        for (int d = 0; d < 64; ++d) {
            float a[4], bb[4];
#pragma unroll
            for (int i = 0; i < 4; ++i) a[i] = buf[d][ty * 4 + i];
#pragma unroll
            for (int j = 0; j < 4; ++j) bb[j] = Msh[d][tx * 4 + j];
#pragma unroll
            for (int i = 0; i < 4; ++i)
#pragma unroll
                for (int j = 0; j < 4; ++j) a2[i][j] += a[i] * bb[j];
        }
#pragma unroll
        for (int i = 0; i < 4; ++i) {
            float4 v;
            v.x = a2[i][0]; v.y = a2[i][1]; v.z = a2[i][2]; v.w = a2[i][3];
            *(float4*)&g_pt[b][c0 + ty * 4 + i][h * 64 + tx * 4] = v;
        }
        __syncthreads();
    }
}

// ---------------------------------------------------------------------------
// Launch
// ---------------------------------------------------------------------------
extern "C" void kernel_launch(void* const* d_in, const int* in_sizes, int n_in,
                              void* d_out, int out_size) {
    const float* x = (const float*)d_in[0];
    const float* w_qkv = (const float*)d_in[1];
    const float* w_o = (const float*)d_in[2];
    float* out = (float*)d_out;

    cudaFuncSetAttribute(gemm_i8, cudaFuncAttributeMaxDynamicSharedMemorySize, SMEM_BYTES);

    unsigned char *xa1, *xa2, *xta1, *xta2, *ga1, *ga2, *wv1, *wv2, *wqt1, *wqt2,
                  *pta1, *pta2, *uta1, *uta2;
    float *sx, *sxt, *sg, *swv, *swqt, *spt, *sut, *gf, *ptf, *utf;
    cudaGetSymbolAddress((void**)&xa1, g_xa1);   cudaGetSymbolAddress((void**)&xa2, g_xa2);
    cudaGetSymbolAddress((void**)&xta1, g_xta1); cudaGetSymbolAddress((void**)&xta2, g_xta2);
    cudaGetSymbolAddress((void**)&ga1, g_ga1);   cudaGetSymbolAddress((void**)&ga2, g_ga2);
    cudaGetSymbolAddress((void**)&wv1, g_wv1);   cudaGetSymbolAddress((void**)&wv2, g_wv2);
    cudaGetSymbolAddress((void**)&wqt1, g_wqt1); cudaGetSymbolAddress((void**)&wqt2, g_wqt2);
    cudaGetSymbolAddress((void**)&pta1, g_pta1); cudaGetSymbolAddress((void**)&pta2, g_pta2);
    cudaGetSymbolAddress((void**)&uta1, g_uta1); cudaGetSymbolAddress((void**)&uta2, g_uta2);
    cudaGetSymbolAddress((void**)&sx, g_sx);     cudaGetSymbolAddress((void**)&sxt, g_sxt);
    cudaGetSymbolAddress((void**)&sg, g_sg);     cudaGetSymbolAddress((void**)&swv, g_swv);
    cudaGetSymbolAddress((void**)&swqt, g_swqt); cudaGetSymbolAddress((void**)&spt, g_spt);
    cudaGetSymbolAddress((void**)&sut, g_sut);
    cudaGetSymbolAddress((void**)&gf, g_gf);
    cudaGetSymbolAddress((void**)&ptf, g_pt);    cudaGetSymbolAddress((void**)&utf, g_utf);

    // 1. transposes (X^T, Wq^T, Wv^T)
    prep_t<<<8192 + 2048, 256>>>(x, w_qkv);
    // 2. all independent quantizes
    quant_all<<<BB * EE + MTOK + EE + EE, 256>>>(x, w_qkv);
    // 3. G = X^T X (triangular; diag extracted; mirrored)
    gemm_i8<<<dim3(36, 1, BB), 256, SMEM_BYTES>>>(
        xta1, xta2, xta1, xta2, sxt, sxt, nullptr, 2048, EE, EE, 0);
    // 4. quantize G
    quantize<<<BB * EE, 256>>>(gf, ga1, ga2, sg, EE);
    // 5. T = G Wv^T (+ diag term)
    gemm_i8<<<dim3(8, 8, BB), 256, SMEM_BYTES>>>(
        ga1, ga2, wv1, wv2, sg, swv, nullptr, 1024, EE, 0, 1);
    // 6. M + P^T fused
    heads<<<dim3(HH, BB), 256>>>(w_qkv, w_o);
    // 7. quantize P^T
    quantize<<<BB * EE, 256>>>(ptf, pta1, pta2, spt, EE);
    // 8. U^T = P^T Wq
    gemm_i8<<<dim3(8, 8, BB), 256, SMEM_BYTES>>>(
        pta1, pta2, wqt1, wqt2, spt, swqt, nullptr, 1024, EE, 0, 2);
    // 9. quantize U^T
    quantize<<<BB * EE, 256>>>(utf, uta1, uta2, sut, EE);
    // 10. out = X U
    gemm_i8<<<dim3(8, SS / 128, BB), 256, SMEM_BYTES>>>(
        xa1, xa2, uta1, uta2, sx, sut, out, 1024, SS, EE, 3);
}

// round 14
// speedup vs baseline: 1.7003x; 1.0115x over previous
#include <cuda_runtime.h>
#include <cstdint>
#include <cstddef>

// Problem constants
#define BB 4
#define SS 2048
#define EE 1024
#define HH 16
#define DD 64
#define MTOK (BB * SS)     // 8192
#define SCALE 0.125f

// int8 GEMM tiling
#define RSTR 80                         // bytes per smem row (64 data + 16 pad)
#define TILEB (128 * RSTR)              // 10240 B per limb tile
#define STAGEB (4 * TILEB)              // A1 A2 B1 B2
#define SMEM_BYTES (2 * STAGEB)         // 81920 B

// Triangular block decode tables for the symmetric G GEMM (36 upper blocks).
__constant__ unsigned char c_tri_i[36] = {
    0,0,0,0,0,0,0,0, 1,1,1,1,1,1,1, 2,2,2,2,2,2, 3,3,3,3,3, 4,4,4,4, 5,5,5, 6,6, 7};
__constant__ unsigned char c_tri_j[36] = {
    0,1,2,3,4,5,6,7, 1,2,3,4,5,6,7, 2,3,4,5,6,7, 3,4,5,6,7, 4,5,6,7, 5,6,7, 6,7, 7};

// ---------------------------------------------------------------------------
// Scratch
// ---------------------------------------------------------------------------
__device__ float g_gf[BB * EE * EE];           // G_off = X^T X minus diag
__device__ float g_gd[BB * EE];                // diag(G)
__device__ float g_tf[BB * EE * EE];           // T = G Wv^T (+diag term)
__device__ float g_wqtf[EE * EE];              // Wq^T [e][j]
__device__ float g_wvtf[EE * EE];              // Wv^T [e][c]
__device__ float g_pt[BB][EE][EE];             // P^T [b][c][j]
__device__ float g_utf[BB * EE * EE];          // U^T [b][c][e]
__device__ int   g_cmax[BB * EE];              // per-(b,e) |X| max (fp32 bits)

__device__ unsigned char g_xa1[MTOK * EE], g_xa2[MTOK * EE];         // X rows
__device__ unsigned char g_xta1[BB * EE * SS], g_xta2[BB * EE * SS]; // X^T rows
__device__ unsigned char g_ga1[BB * EE * EE], g_ga2[BB * EE * EE];
__device__ unsigned char g_wv1[EE * EE], g_wv2[EE * EE];
__device__ unsigned char g_wqt1[EE * EE], g_wqt2[EE * EE];
__device__ unsigned char g_pta1[BB * EE * EE], g_pta2[BB * EE * EE];
__device__ unsigned char g_uta1[BB * EE * EE], g_uta2[BB * EE * EE];
__device__ float g_sx[MTOK], g_sxt[BB * EE], g_sg[BB * EE], g_swv[EE],
                 g_swqt[EE], g_spt[BB * EE], g_sut[BB * EE];

// ---------------------------------------------------------------------------
// Helpers
// ---------------------------------------------------------------------------
__device__ __forceinline__ uint32_t smem_u32(const void* p) {
    uint32_t a;
    asm("{ .reg .u64 t; cvta.to.shared.u64 t, %1; cvt.u32.u64 %0, t; }" : "=r"(a) : "l"(p));
    return a;
}
__device__ __forceinline__ void cpasync16(uint32_t s, const void* g) {
    asm volatile("cp.async.cg.shared.global [%0], [%1], 16;" :: "r"(s), "l"(g));
}
#define CP_COMMIT() asm volatile("cp.async.commit_group;" ::: "memory")
#define CP_WAIT(n)  asm volatile("cp.async.wait_group %0;" :: "n"(n) : "memory")

__device__ __forceinline__ void imma(int* c, const uint32_t* a, const uint32_t* b) {
    asm volatile(
        "mma.sync.aligned.m16n8k32.row.col.s32.s8.s8.s32 "
        "{%0,%1,%2,%3}, {%4,%5,%6,%7}, {%8,%9}, {%0,%1,%2,%3};"
        : "+r"(c[0]), "+r"(c[1]), "+r"(c[2]), "+r"(c[3])
        : "r"(a[0]), "r"(a[1]), "r"(a[2]), "r"(a[3]), "r"(b[0]), "r"(b[1]));
}

// Pack 4 s32 (range fits s8) into one u32: bytes [b0,b1,b2,b3].
__device__ __forceinline__ uint32_t pack4(int b0, int b1, int b2, int b3) {
    uint32_t t, r;
    asm("cvt.pack.sat.s8.s32.b32 %0, %1, %2, 0;" : "=r"(t) : "r"(b3), "r"(b2));
    asm("cvt.pack.sat.s8.s32.b32 %0, %1, %2, %3;" : "=r"(r) : "r"(b1), "r"(b0), "r"(t));
    return r;
}

// Quantize one fp32 value: q1 = rint(v*inv), q2 = rint((v*inv-q1)*252)
__device__ __forceinline__ void qsplit(float v, float inv, int& q1, int& q2) {
    float t = v * inv;
    q1 = __float2int_rn(t);
    q2 = __float2int_rn((t - (float)q1) * 252.0f);
}

// ---------------------------------------------------------------------------
// clear_cmax: zero the column-max accumulators (replaces cudaMemsetAsync).
// ---------------------------------------------------------------------------
__global__ __launch_bounds__(256) void clear_cmax() {
    g_cmax[blockIdx.x * 1024 + threadIdx.x * 4 + 0] = 0;
    g_cmax[blockIdx.x * 1024 + threadIdx.x * 4 + 1] = 0;
    g_cmax[blockIdx.x * 1024 + threadIdx.x * 4 + 2] = 0;
    g_cmax[blockIdx.x * 1024 + threadIdx.x * 4 + 3] = 0;
}

// ---------------------------------------------------------------------------
// quant_row_256: one 256-thread block quantizes one fp32 row (len 1024/2048)
// into two s8 limbs + scale.
// ---------------------------------------------------------------------------
__device__ __forceinline__ void quant_row_256(const float* __restrict__ src,
                                              unsigned char* __restrict__ q1,
                                              unsigned char* __restrict__ q2,
                                              float* __restrict__ sdeq, int len) {
    const int tid = threadIdx.x;
    const int L = len >> 10;
    const float4* p = (const float4*)src;

    __shared__ float wmax[8];
    __shared__ float sinv;

    float4 v[2];
    float m = 0.0f;
    for (int i = 0; i < L; ++i) {
        v[i] = p[tid + i * 256];
        m = fmaxf(m, fmaxf(fmaxf(fabsf(v[i].x), fabsf(v[i].y)),
                           fmaxf(fabsf(v[i].z), fabsf(v[i].w))));
    }
#pragma unroll
    for (int o = 16; o > 0; o >>= 1) m = fmaxf(m, __shfl_xor_sync(0xFFFFFFFFu, m, o));
    if ((tid & 31) == 0) wmax[tid >> 5] = m;
    __syncthreads();
    if (tid == 0) {
        float mm = wmax[0];
#pragma unroll
        for (int i = 1; i < 8; ++i) mm = fmaxf(mm, wmax[i]);
        *sdeq = mm * (1.0f / 126.0f);
        sinv = (mm > 0.0f) ? 126.0f / mm : 0.0f;
    }
    __syncthreads();
    const float inv = sinv;

    for (int i = 0; i < L; ++i) {
        int a0, a1, a2, a3, b0, b1, b2, b3;
        qsplit(v[i].x, inv, a0, b0);
        qsplit(v[i].y, inv, a1, b1);
        qsplit(v[i].z, inv, a2, b2);
        qsplit(v[i].w, inv, a3, b3);
        ((uint32_t*)q1)[tid + i * 256] = pack4(a0, a1, a2, a3);
        ((uint32_t*)q2)[tid + i * 256] = pack4(b0, b1, b2, b3);
    }
}

// Generic single-source quantize (G / Pt / Ut stages).
__global__ __launch_bounds__(256) void quantize(const float* __restrict__ src,
                                                unsigned char* __restrict__ q1,
                                                unsigned char* __restrict__ q2,
                                                float* __restrict__ sdeq, int len) {
    const int row = blockIdx.x;
    quant_row_256(src + (size_t)row * len, q1 + (size_t)row * len,
                  q2 + (size_t)row * len, sdeq + row, len);
}

// ---------------------------------------------------------------------------
// stage1: [0,256) colmax of X (per (b,e)); [256,2304) Wq/Wv gather-transpose.
// ---------------------------------------------------------------------------
__global__ __launch_bounds__(256) void stage1(const float* __restrict__ x,
                                              const float* __restrict__ w) {
    const int bid = blockIdx.x;
    const int tid = threadIdx.x;

    if (bid < 256) {
        const int b = bid >> 6;
        const int s0 = (bid & 63) * 32;
        float m0 = 0, m1 = 0, m2 = 0, m3 = 0;
        const float4* p = (const float4*)(x + ((size_t)b * SS + s0) * EE) + tid;
#pragma unroll 4
        for (int r = 0; r < 32; ++r) {
            float4 v = p[r * 256];
            m0 = fmaxf(m0, fabsf(v.x));
            m1 = fmaxf(m1, fabsf(v.y));
            m2 = fmaxf(m2, fabsf(v.z));
            m3 = fmaxf(m3, fabsf(v.w));
        }
        int* dst = g_cmax + b * EE + tid * 4;
        atomicMax(dst + 0, __float_as_int(m0));
        atomicMax(dst + 1, __float_as_int(m1));
        atomicMax(dst + 2, __float_as_int(m2));
        atomicMax(dst + 3, __float_as_int(m3));
    } else {
        __shared__ float t[32][33];
        const int tt = bid - 256;
        const int which = tt >> 10;           // 0 -> Wq^T, 1 -> Wv^T
        const int rem = tt & 1023;
        const int e0 = (rem & 31) * 32;
        const int j0 = (rem >> 5) * 32;
        const int off = which ? 128 : 0;
        float* dst = which ? g_wvtf : g_wqtf;
        const int c = tid & 31, r0 = tid >> 5;
#pragma unroll
        for (int p = 0; p < 4; ++p) {
            const int j = j0 + r0 + p * 8;
            const int srow = (j >> 6) * 192 + off + (j & 63);
            t[r0 + p * 8][c] = w[(size_t)srow * EE + e0 + c];
        }
        __syncthreads();
#pragma unroll
        for (int p = 0; p < 4; ++p) {
            const int r = r0 + p * 8;
            dst[(size_t)(e0 + r) * EE + j0 + c] = t[c][r];
        }
    }
}

// ---------------------------------------------------------------------------
// stage2: fused quantization.
//  [0,2048): X^T transpose+quantize tiles (128 s x 32 e), scales from g_cmax
//  [2048,10240): X rows (self-scaling)
//  [10240,11264): Wv rows gathered
//  [11264,12288): Wq^T rows
// ---------------------------------------------------------------------------
__global__ __launch_bounds__(256) void stage2(const float* __restrict__ x,
                                              const float* __restrict__ w) {
    const int bid = blockIdx.x;
    const int tid = threadIdx.x;

    if (bid < 2048) {
        __shared__ float ts[32][133];
        const int b = bid >> 9;               // 512 tiles per batch
        const int rem = bid & 511;
        const int s0 = (rem & 15) * 128;
        const int e0 = (rem >> 4) * 32;

        // Read 128 s-rows x 32 e, store transposed into smem.
#pragma unroll
        for (int i = 0; i < 4; ++i) {
            const int idx = i * 256 + tid;
            const int sl = idx >> 3;
            const int e4 = (idx & 7) * 4;
            float4 v = *(const float4*)&x[((size_t)b * SS + s0 + sl) * EE + e0 + e4];
            ts[e4 + 0][sl] = v.x; ts[e4 + 1][sl] = v.y;
            ts[e4 + 2][sl] = v.z; ts[e4 + 3][sl] = v.w;
        }
        __syncthreads();

        // Write: thread -> (e_local, 16-s segment), quantize with colmax scale.
        const int el = tid >> 3;
        const int sg = (tid & 7) * 16;
        const float cm = __int_as_float(g_cmax[b * EE + e0 + el]);
        const float inv = (cm > 0.0f) ? 126.0f / cm : 0.0f;
        if (s0 == 0 && (tid & 7) == 0) g_sxt[b * EE + e0 + el] = cm * (1.0f / 126.0f);

        uint32_t o1[4], o2[4];
#pragma unroll
        for (int q = 0; q < 4; ++q) {
            int a0, a1, a2, a3, b0, b1, b2, b3;
            qsplit(ts[el][sg + q * 4 + 0], inv, a0, b0);
            qsplit(ts[el][sg + q * 4 + 1], inv, a1, b1);
            qsplit(ts[el][sg + q * 4 + 2], inv, a2, b2);
            qsplit(ts[el][sg + q * 4 + 3], inv, a3, b3);
            o1[q] = pack4(a0, a1, a2, a3);
            o2[q] = pack4(b0, b1, b2, b3);
        }
        const size_t go = ((size_t)(b * EE + e0 + el)) * SS + s0 + sg;
        *(uint4*)&g_xta1[go] = make_uint4(o1[0], o1[1], o1[2], o1[3]);
        *(uint4*)&g_xta2[go] = make_uint4(o2[0], o2[1], o2[2], o2[3]);
    } else if (bid < 2048 + MTOK) {
        const int r = bid - 2048;
        quant_row_256(x + (size_t)r * EE, g_xa1 + (size_t)r * EE,
                      g_xa2 + (size_t)r * EE, g_sx + r, EE);
    } else if (bid < 2048 + MTOK + EE) {
        const int r = bid - 2048 - MTOK;
        const int sr = (r >> 6) * 192 + 128 + (r & 63);
        quant_row_256(w + (size_t)sr * EE, g_wv1 + (size_t)r * EE,
                      g_wv2 + (size_t)r * EE, g_swv + r, EE);
    } else {
        const int r = bid - 2048 - MTOK - EE;
        quant_row_256(g_wqtf + (size_t)r * EE, g_wqt1 + (size_t)r * EE,
                      g_wqt2 + (size_t)r * EE, g_swqt + r, EE);
    }
}

// ---------------------------------------------------------------------------
// int8 2-limb GEMM core — single instantiation, mode-parameterized.
// emode 0: G = XT@XT^T (triangular LUT grid, diag extracted, mirrored), kd=2048
// emode 1: T = G@Wv^T + diag term.  emode 2: U^T = Pt@WqT^T.
// emode 3: out = X@U (row = z*SS + local).
// ---------------------------------------------------------------------------
__global__ __launch_bounds__(256, 1) void gemm_i8(
    const unsigned char* __restrict__ A1b, const unsigned char* __restrict__ A2b,
    const unsigned char* __restrict__ B1b, const unsigned char* __restrict__ B2b,
    const float* __restrict__ sAb, const float* __restrict__ sBb,
    float* __restrict__ Out, int kd, int aZ, int bZ, int emode) {
    extern __shared__ unsigned char smem[];
    const int tid = threadIdx.x;
    const int wid = tid >> 5, lane = tid & 31;
    const int g = lane >> 2, tg = lane & 3;
    const int warp_m = wid & 3;
    const int warp_n = wid >> 2;
    const int z = blockIdx.z;

    int bm, bn;
    if (emode == 0) {
        bm = (int)c_tri_i[blockIdx.x] * 128;
        bn = (int)c_tri_j[blockIdx.x] * 128;
    } else {
        bn = blockIdx.x * 128;
        bm = blockIdx.y * 128;
    }

    const unsigned char* A1 = A1b + (size_t)(z * aZ + bm) * kd;
    const unsigned char* A2 = A2b + (size_t)(z * aZ + bm) * kd;
    const unsigned char* B1 = B1b + (size_t)(z * bZ + bn) * kd;
    const unsigned char* B2 = B2b + (size_t)(z * bZ + bn) * kd;
    const float* sA = sAb + z * aZ + bm;
    const float* sB = sBb + z * bZ + bn;

    const uint32_t sb = smem_u32(smem);

    int acc11[2][8][4], accmx[2][8][4];
#pragma unroll
    for (int mt = 0; mt < 2; ++mt)
#pragma unroll
        for (int nt = 0; nt < 8; ++nt)
#pragma unroll
            for (int i = 0; i < 4; ++i) { acc11[mt][nt][i] = 0; accmx[mt][nt][i] = 0; }

    auto load_chunk = [&](int s, int k0) {
        const uint32_t base = sb + s * STAGEB;
#pragma unroll
        for (int it = 0; it < 2; ++it) {
            const int id = tid + it * 256;
            const int row = id >> 2;
            const int c16 = (id & 3) * 16;
            const uint32_t so = row * RSTR + c16;
            const size_t go = (size_t)row * kd + k0 + c16;
            cpasync16(base + so,              A1 + go);
            cpasync16(base + TILEB + so,      A2 + go);
            cpasync16(base + 2 * TILEB + so,  B1 + go);
            cpasync16(base + 3 * TILEB + so,  B2 + go);
        }
        CP_COMMIT();
    };

    load_chunk(0, 0);

    const int NK = kd >> 6;
    for (int kc = 0; kc < NK; ++kc) {
        const int s = kc & 1;
        if (kc + 1 < NK) {
            load_chunk(1 - s, (kc + 1) * 64);
            CP_WAIT(1);
        } else {
            CP_WAIT(0);
        }
        __syncthreads();

        const uint32_t stg = sb + s * STAGEB;
#pragma unroll
        for (int ks = 0; ks < 2; ++ks) {
            const uint32_t kof = ks * 32 + tg * 4;
            uint32_t a1f[2][4], a2f[2][4], b1f[8][2], b2f[8][2];
#pragma unroll
            for (int mt = 0; mt < 2; ++mt) {
                const uint32_t r0 = stg + (warp_m * 32 + mt * 16 + g) * RSTR + kof;
#pragma unroll
                for (int limb = 0; limb < 2; ++limb) {
                    uint32_t* f = limb ? a2f[mt] : a1f[mt];
                    const uint32_t rr = r0 + limb * TILEB;
                    asm volatile("ld.shared.b32 %0, [%1];" : "=r"(f[0]) : "r"(rr));
                    asm volatile("ld.shared.b32 %0, [%1];" : "=r"(f[1]) : "r"(rr + 8 * RSTR));
                    asm volatile("ld.shared.b32 %0, [%1];" : "=r"(f[2]) : "r"(rr + 16));
                    asm volatile("ld.shared.b32 %0, [%1];" : "=r"(f[3]) : "r"(rr + 8 * RSTR + 16));
                }
            }
#pragma unroll
            for (int nt = 0; nt < 8; ++nt) {
                const uint32_t r0 = stg + 2 * TILEB + (warp_n * 64 + nt * 8 + g) * RSTR + kof;
                asm volatile("ld.shared.b32 %0, [%1];" : "=r"(b1f[nt][0]) : "r"(r0));
                asm volatile("ld.shared.b32 %0, [%1];" : "=r"(b1f[nt][1]) : "r"(r0 + 16));
                asm volatile("ld.shared.b32 %0, [%1];" : "=r"(b2f[nt][0]) : "r"(r0 + TILEB));
                asm volatile("ld.shared.b32 %0, [%1];" : "=r"(b2f[nt][1]) : "r"(r0 + TILEB + 16));
            }
#pragma unroll
            for (int mt = 0; mt < 2; ++mt)
#pragma unroll
                for (int nt = 0; nt < 8; ++nt) imma(acc11[mt][nt], a1f[mt], b1f[nt]);
#pragma unroll
            for (int mt = 0; mt < 2; ++mt)
#pragma unroll
                for (int nt = 0; nt < 8; ++nt) imma(accmx[mt][nt], a1f[mt], b2f[nt]);
#pragma unroll
            for (int mt = 0; mt < 2; ++mt)
#pragma unroll
                for (int nt = 0; nt < 8; ++nt) imma(accmx[mt][nt], a2f[mt], b1f[nt]);
        }
        __syncthreads();
    }

    // Epilogue: dequant + runtime-mode store.
#pragma unroll
    for (int mt = 0; mt < 2; ++mt) {
        const int rb = warp_m * 32 + mt * 16 + g;
        const float sa0 = sA[rb], sa1 = sA[rb + 8];
#pragma unroll
        for (int nt = 0; nt < 8; ++nt) {
            const int coff = warp_n * 64 + nt * 8 + 2 * tg;
            const float sb0 = sB[coff], sb1 = sB[coff + 1];
            const int col = bn + coff;
#pragma unroll
            for (int half = 0; half < 2; ++half) {
                const int rl = bm + rb + half * 8;
                const float sa = half ? sa1 : sa0;
                float v0 = ((float)acc11[mt][nt][half * 2 + 0]
                            + (float)accmx[mt][nt][half * 2 + 0] * (1.0f / 252.0f)) * sa * sb0;
                float v1 = ((float)acc11[mt][nt][half * 2 + 1]
                            + (float)accmx[mt][nt][half * 2 + 1] * (1.0f / 252.0f)) * sa * sb1;
                if (emode == 0) {
                    if (rl == col)     { g_gd[z * EE + rl] = v0; v0 = 0.0f; }
                    if (rl == col + 1) { g_gd[z * EE + rl] = v1; v1 = 0.0f; }
                    *(float2*)&g_gf[((size_t)z * EE + rl) * EE + col] = make_float2(v0, v1);
                    if (bm != bn) {   // mirror into lower triangle (exact copy)
                        g_gf[((size_t)z * EE + col) * EE + rl] = v0;
                        g_gf[((size_t)z * EE + col + 1) * EE + rl] = v1;
                    }
                } else if (emode == 1) {
                    const float gd = g_gd[z * EE + rl];
                    const float2 wv = *(const float2*)&g_wvtf[(size_t)rl * EE + col];
                    v0 += gd * wv.x;
                    v1 += gd * wv.y;
                    *(float2*)&g_tf[((size_t)z * EE + rl) * EE + col] = make_float2(v0, v1);
                } else if (emode == 2) {
                    *(float2*)&g_utf[((size_t)z * EE + rl) * EE + col] = make_float2(v0, v1);
                } else {
                    *(float2*)&Out[((size_t)z * SS + rl) * EE + col] = make_float2(v0, v1);
                }
            }
        }
    }
}

// ---------------------------------------------------------------------------
// heads: fused mstep + make_p.  Grid (HH, BB), 256 threads.
// ---------------------------------------------------------------------------
__global__ __launch_bounds__(256) void heads(const float* __restrict__ w,
                                             const float* __restrict__ w_o) {
    const int h = blockIdx.x, b = blockIdx.y;
    const int tid = threadIdx.x;
    const int tx = tid & 15;
    const int ty = tid >> 4;

    __shared__ float Msh[64][68];
    __shared__ float buf[64][68];

    float acc[4][4];
#pragma unroll
    for (int i = 0; i < 4; ++i)
#pragma unroll
        for (int j = 0; j < 4; ++j) acc[i][j] = 0.0f;

    for (int e0 = 0; e0 < EE; e0 += 32) {
#pragma unroll
        for (int it = 0; it < 2; ++it) {
            const int fid = tid + it * 256;
            const int d1 = fid >> 3;
            const int c4 = (fid & 7) * 4;
            float4 v = *(const float4*)&w[(size_t)(h * 192 + 64 + d1) * EE + e0 + c4];
            buf[c4 + 0][d1] = v.x; buf[c4 + 1][d1] = v.y;
            buf[c4 + 2][d1] = v.z; buf[c4 + 3][d1] = v.w;
        }
#pragma unroll
        for (int it = 0; it < 2; ++it) {
            const int fid = tid + it * 256;
            const int r = fid >> 4;
            const int c4 = (fid & 15) * 4;
            *(float4*)&buf[32 + r][c4] =
                *(const float4*)&g_tf[((size_t)b * EE + e0 + r) * EE + h * 64 + c4];
        }
        __syncthreads();
#pragma unroll 8
        for (int e = 0; e < 32; ++e) {
            float a[4], bb[4];
#pragma unroll
            for (int i = 0; i < 4; ++i) a[i] = buf[e][ty * 4 + i];
#pragma unroll
            for (int j = 0; j < 4; ++j) bb[j] = buf[32 + e][tx * 4 + j];
#pragma unroll
            for (int i = 0; i < 4; ++i)
#pragma unroll
                for (int j = 0; j < 4; ++j) acc[i][j] += a[i] * bb[j];
        }
        __syncthreads();
    }
#pragma unroll
    for (int i = 0; i < 4; ++i)
#pragma unroll
        for (int j = 0; j < 4; ++j)
            Msh[tx * 4 + j][ty * 4 + i] = SCALE * acc[i][j];
    __syncthreads();

    for (int c0 = 0; c0 < EE; c0 += 64) {
#pragma unroll
        for (int it = 0; it < 4; ++it) {
            const int fid = tid + it * 256;
            const int c = fid >> 4;
            const int d4 = (fid & 15) * 4;
            float4 v = *(const float4*)&w_o[(size_t)(c0 + c) * EE + h * 64 + d4];
            buf[d4 + 0][c] = v.x; buf[d4 + 1][c] = v.y;
            buf[d4 + 2][c] = v.z; buf[d4 + 3][c] = v.w;
        }
        __syncthreads();

        float a2[4][4];
#pragma unroll
        for (int i = 0; i < 4; ++i)
#pragma unroll
            for (int j = 0; j < 4; ++j) a2[i][j] = 0.0f;
#pragma unroll 8
        for (int d = 0; d < 64; ++d) {
            float a[4], bb[4];
#pragma unroll
            for (int i = 0; i < 4; ++i) a[i] = buf[d][ty * 4 + i];
#pragma unroll
            for (int j = 0; j < 4; ++j) bb[j] = Msh[d][tx * 4 + j];
#pragma unroll
            for (int i = 0; i < 4; ++i)
#pragma unroll
                for (int j = 0; j < 4; ++j) a2[i][j] += a[i] * bb[j];
        }
#pragma unroll
        for (int i = 0; i < 4; ++i) {
            float4 v;
            v.x = a2[i][0]; v.y = a2[i][1]; v.z = a2[i][2]; v.w = a2[i][3];
            *(float4*)&g_pt[b][c0 + ty * 4 + i][h * 64 + tx * 4] = v;
        }
        __syncthreads();
    }
}

// ---------------------------------------------------------------------------
// Launch
// ---------------------------------------------------------------------------
extern "C" void kernel_launch(void* const* d_in, const int* in_sizes, int n_in,
                              void* d_out, int out_size) {
    const float* x = (const float*)d_in[0];
    const float* w_qkv = (const float*)d_in[1];
    const float* w_o = (const float*)d_in[2];
    float* out = (float*)d_out;

    cudaFuncSetAttribute(gemm_i8, cudaFuncAttributeMaxDynamicSharedMemorySize, SMEM_BYTES);

    unsigned char *xa1, *xa2, *xta1, *xta2, *ga1, *ga2, *wv1, *wv2, *wqt1, *wqt2,
                  *pta1, *pta2, *uta1, *uta2;
    float *sx, *sxt, *sg, *swv, *swqt, *spt, *sut, *gf, *ptf, *utf;
    cudaGetSymbolAddress((void**)&xa1, g_xa1);   cudaGetSymbolAddress((void**)&xa2, g_xa2);
    cudaGetSymbolAddress((void**)&xta1, g_xta1); cudaGetSymbolAddress((void**)&xta2, g_xta2);
    cudaGetSymbolAddress((void**)&ga1, g_ga1);   cudaGetSymbolAddress((void**)&ga2, g_ga2);
    cudaGetSymbolAddress((void**)&wv1, g_wv1);   cudaGetSymbolAddress((void**)&wv2, g_wv2);
    cudaGetSymbolAddress((void**)&wqt1, g_wqt1); cudaGetSymbolAddress((void**)&wqt2, g_wqt2);
    cudaGetSymbolAddress((void**)&pta1, g_pta1); cudaGetSymbolAddress((void**)&pta2, g_pta2);
    cudaGetSymbolAddress((void**)&uta1, g_uta1); cudaGetSymbolAddress((void**)&uta2, g_uta2);
    cudaGetSymbolAddress((void**)&sx, g_sx);     cudaGetSymbolAddress((void**)&sxt, g_sxt);
    cudaGetSymbolAddress((void**)&sg, g_sg);     cudaGetSymbolAddress((void**)&swv, g_swv);
    cudaGetSymbolAddress((void**)&swqt, g_swqt); cudaGetSymbolAddress((void**)&spt, g_spt);
    cudaGetSymbolAddress((void**)&sut, g_sut);
    cudaGetSymbolAddress((void**)&gf, g_gf);
    cudaGetSymbolAddress((void**)&ptf, g_pt);    cudaGetSymbolAddress((void**)&utf, g_utf);

    // 0. clear column-max accumulators
    clear_cmax<<<4, 256>>>();
    // 1. colmax(X) + weight transposes
    stage1<<<256 + 2048, 256>>>(x, w_qkv);
    // 2. fused quantization: X^T (transpose+quant), X rows, Wv, Wq^T
    stage2<<<2048 + MTOK + EE + EE, 256>>>(x, w_qkv);
    // 3. G = X^T X (triangular; diag extracted; mirrored)
    gemm_i8<<<dim3(36, 1, BB), 256, SMEM_BYTES>>>(
        xta1, xta2, xta1, xta2, sxt, sxt, nullptr, 2048, EE, EE, 0);
    // 4. quantize G
    quantize<<<BB * EE, 256>>>(gf, ga1, ga2, sg, EE);
    // 5. T = G Wv^T (+ diag term)
    gemm_i8<<<dim3(8, 8, BB), 256, SMEM_BYTES>>>(
        ga1, ga2, wv1, wv2, sg, swv, nullptr, 1024, EE, 0, 1);
    // 6. M + P^T fused
    heads<<<dim3(HH, BB), 256>>>(w_qkv, w_o);
    // 7. quantize P^T
    quantize<<<BB * EE, 256>>>(ptf, pta1, pta2, spt, EE);
    // 8. U^T = P^T Wq
    gemm_i8<<<dim3(8, 8, BB), 256, SMEM_BYTES>>>(
        pta1, pta2, wqt1, wqt2, spt, swqt, nullptr, 1024, EE, 0, 2);
    // 9. quantize U^T
    quantize<<<BB * EE, 256>>>(utf, uta1, uta2, sut, EE);
    // 10. out = X U
    gemm_i8<<<dim3(8, SS / 128, BB), 256, SMEM_BYTES>>>(
        xa1, xa2, uta1, uta2, sx, sut, out, 1024, SS, EE, 3);
}